// round 11
// baseline (speedup 1.0000x reference)
#include <cuda_runtime.h>
#include <cstdint>
#include <math.h>

// Shapes fixed: B=4, T=256, C=2048, U=4, D=512, P=512, H=8, dk=64

__device__ float2 g_stats[11264];   // mu/rstd for q(1024)|k(8192)|v(2048) rows
__device__ float2 g_stats4[1024];   // mu/rstd for LN4
__device__ float g_q  [1024 * 512];
__device__ float g_k  [8192 * 512];
__device__ float g_v  [2048 * 512];
__device__ float g_att[1024 * 512];
__device__ float g_o  [1024 * 512];

typedef unsigned long long u64;

__device__ __forceinline__ u64 pk2(float lo, float hi) {
    u64 r; asm("mov.b64 %0, {%1, %2};" : "=l"(r) : "f"(lo), "f"(hi)); return r;
}
__device__ __forceinline__ void upk2(u64 v, float& lo, float& hi) {
    asm("mov.b64 {%0, %1}, %2;" : "=f"(lo), "=f"(hi) : "l"(v));
}
__device__ __forceinline__ u64 fma2(u64 a, u64 b, u64 c) {
    u64 d; asm("fma.rn.f32x2 %0, %1, %2, %3;" : "=l"(d) : "l"(a), "l"(b), "l"(c)); return d;
}
__device__ __forceinline__ u64 mul2(u64 a, u64 b) {
    u64 d; asm("mul.rn.f32x2 %0, %1, %2;" : "=l"(d) : "l"(a), "l"(b)); return d;
}
__device__ __forceinline__ uint32_t smem_u32(const void* p) {
    uint32_t a;
    asm("{ .reg .u64 t; cvta.to.shared.u64 t, %1; cvt.u32.u64 %0, t; }" : "=r"(a) : "l"(p));
    return a;
}
#define CP_ASYNC16(dst, src) \
    asm volatile("cp.async.cg.shared.global [%0], [%1], 16;" :: "r"(dst), "l"(src) : "memory")
#define CP_COMMIT() asm volatile("cp.async.commit_group;" ::: "memory")
#define CP_WAIT(n)  asm volatile("cp.async.wait_group %0;" :: "n"(n) : "memory")

// ---------------------------------------------------------------------------
// zero both accumulation buffers (g_o, d_out): 2 x 524288 floats.
// ---------------------------------------------------------------------------
__global__ __launch_bounds__(256) void zero2(float* __restrict__ a, float* __restrict__ b)
{
    int i = blockIdx.x * 256 + threadIdx.x;
    if (i < 131072) *(float4*)&a[i * 4] = make_float4(0.f, 0.f, 0.f, 0.f);
    else { i -= 131072; *(float4*)&b[i * 4] = make_float4(0.f, 0.f, 0.f, 0.f); }
}

// ---------------------------------------------------------------------------
// LN stats: one warp per row, D=512. Writes (mu, rstd).
// ---------------------------------------------------------------------------
__device__ __forceinline__ void ln_stat_row(
    const float* __restrict__ xr, float2* __restrict__ out, int lane)
{
    float s = 0.f, ss = 0.f;
    #pragma unroll
    for (int j = 0; j < 4; ++j) {
        float4 x = *(const float4*)&xr[j * 128 + lane * 4];
        s  += x.x + x.y + x.z + x.w;
        ss += x.x * x.x + x.y * x.y + x.z * x.z + x.w * x.w;
    }
    #pragma unroll
    for (int o = 16; o; o >>= 1) {
        s  += __shfl_xor_sync(0xffffffffu, s, o);
        ss += __shfl_xor_sync(0xffffffffu, ss, o);
    }
    if (lane == 0) {
        float mu = s * (1.f / 512.f);
        float rstd = rsqrtf(ss * (1.f / 512.f) - mu * mu + 1e-5f);
        *out = make_float2(mu, rstd);
    }
}

__global__ __launch_bounds__(256) void ln_stats3(
    const float* __restrict__ x0, const float* __restrict__ x1,
    const float* __restrict__ x2, float2* __restrict__ st)
{
    const int lane = threadIdx.x & 31;
    const int wr = threadIdx.x >> 5;
    const int bx = blockIdx.x;
    const float* x; size_t row; float2* o;
    if (bx < 128)       { x = x0; row = (size_t)bx * 8 + wr; o = st; }
    else if (bx < 1152) { x = x1; row = (size_t)(bx - 128) * 8 + wr; o = st + 1024; }
    else                { x = x2; row = (size_t)(bx - 1152) * 8 + wr; o = st + 9216; }
    ln_stat_row(x + row * 512, o + row, lane);
}

__global__ __launch_bounds__(256) void ln_stats1(
    const float* __restrict__ x, float2* __restrict__ st)
{
    const int lane = threadIdx.x & 31;
    const size_t row = (size_t)blockIdx.x * 8 + (threadIdx.x >> 5);
    ln_stat_row(x + row * 512, st + row, lane);
}

// ---------------------------------------------------------------------------
// sgemm_big with fused LN on A-load: 128x128 tile, BK=16, 256 thr, 8x8 tile.
// launch_bounds (256,2): cap regs at 128 so 2 CTAs/SM co-reside.
// ---------------------------------------------------------------------------
__device__ __forceinline__ void sgemm_big_body_ln(
    const float* __restrict__ A, const float2* __restrict__ stats,
    const float* __restrict__ lnw, const float* __restrict__ lnb,
    const float* __restrict__ B, const float* __restrict__ bias,
    float* __restrict__ C, size_t m0, int n0)
{
    __shared__ float As[2][16][132];
    __shared__ float Bs[2][16][132];

    const int tid = threadIdx.x;
    const int ty = tid >> 4, tx = tid & 15;
    const int ar = tid >> 1, ak4 = (tid & 1) * 8;
    const int bk = tid >> 4, bn = (tid & 15) * 8;

    const float2 st = stats[m0 + ar];

    u64 acc[8][4];
    #pragma unroll
    for (int i = 0; i < 8; ++i)
        #pragma unroll
        for (int j = 0; j < 4; ++j) acc[i][j] = 0ull;

    float4 la0, la1, lb0, lb1;
    {
        float4 r0 = *(const float4*)&A[(m0 + ar) * 512 + ak4];
        float4 r1 = *(const float4*)&A[(m0 + ar) * 512 + ak4 + 4];
        float4 w0 = *(const float4*)&lnw[ak4];
        float4 w1 = *(const float4*)&lnw[ak4 + 4];
        float4 b0 = *(const float4*)&lnb[ak4];
        float4 b1 = *(const float4*)&lnb[ak4 + 4];
        la0.x = (r0.x - st.x) * st.y * w0.x + b0.x;
        la0.y = (r0.y - st.x) * st.y * w0.y + b0.y;
        la0.z = (r0.z - st.x) * st.y * w0.z + b0.z;
        la0.w = (r0.w - st.x) * st.y * w0.w + b0.w;
        la1.x = (r1.x - st.x) * st.y * w1.x + b1.x;
        la1.y = (r1.y - st.x) * st.y * w1.y + b1.y;
        la1.z = (r1.z - st.x) * st.y * w1.z + b1.z;
        la1.w = (r1.w - st.x) * st.y * w1.w + b1.w;
    }
    lb0 = *(const float4*)&B[(size_t)bk * 512 + n0 + bn];
    lb1 = *(const float4*)&B[(size_t)bk * 512 + n0 + bn + 4];
    {
        As[0][ak4 + 0][ar] = la0.x; As[0][ak4 + 1][ar] = la0.y;
        As[0][ak4 + 2][ar] = la0.z; As[0][ak4 + 3][ar] = la0.w;
        As[0][ak4 + 4][ar] = la1.x; As[0][ak4 + 5][ar] = la1.y;
        As[0][ak4 + 6][ar] = la1.z; As[0][ak4 + 7][ar] = la1.w;
        *(float4*)&Bs[0][bk][bn]     = lb0;
        *(float4*)&Bs[0][bk][bn + 4] = lb1;
    }
    __syncthreads();

    for (int kt = 0; kt < 32; ++kt) {
        const int buf = kt & 1;
        if (kt < 31) {
            const int k0 = (kt + 1) * 16;
            float4 r0 = *(const float4*)&A[(m0 + ar) * 512 + k0 + ak4];
            float4 r1 = *(const float4*)&A[(m0 + ar) * 512 + k0 + ak4 + 4];
            float4 w0 = *(const float4*)&lnw[k0 + ak4];
            float4 w1 = *(const float4*)&lnw[k0 + ak4 + 4];
            float4 b0 = *(const float4*)&lnb[k0 + ak4];
            float4 b1 = *(const float4*)&lnb[k0 + ak4 + 4];
            la0.x = (r0.x - st.x) * st.y * w0.x + b0.x;
            la0.y = (r0.y - st.x) * st.y * w0.y + b0.y;
            la0.z = (r0.z - st.x) * st.y * w0.z + b0.z;
            la0.w = (r0.w - st.x) * st.y * w0.w + b0.w;
            la1.x = (r1.x - st.x) * st.y * w1.x + b1.x;
            la1.y = (r1.y - st.x) * st.y * w1.y + b1.y;
            la1.z = (r1.z - st.x) * st.y * w1.z + b1.z;
            la1.w = (r1.w - st.x) * st.y * w1.w + b1.w;
            lb0 = *(const float4*)&B[(size_t)(k0 + bk) * 512 + n0 + bn];
            lb1 = *(const float4*)&B[(size_t)(k0 + bk) * 512 + n0 + bn + 4];
        }
        #pragma unroll
        for (int kk = 0; kk < 16; ++kk) {
            float4 a0 = *(const float4*)&As[buf][kk][ty * 8];
            float4 a1 = *(const float4*)&As[buf][kk][ty * 8 + 4];
            u64 b0 = *(const u64*)&Bs[buf][kk][2 * tx];
            u64 b1 = *(const u64*)&Bs[buf][kk][2 * tx + 32];
            u64 b2 = *(const u64*)&Bs[buf][kk][2 * tx + 64];
            u64 b3 = *(const u64*)&Bs[buf][kk][2 * tx + 96];
            float av[8] = {a0.x, a0.y, a0.z, a0.w, a1.x, a1.y, a1.z, a1.w};
            #pragma unroll
            for (int i = 0; i < 8; ++i) {
                u64 ai = pk2(av[i], av[i]);
                acc[i][0] = fma2(ai, b0, acc[i][0]);
                acc[i][1] = fma2(ai, b1, acc[i][1]);
                acc[i][2] = fma2(ai, b2, acc[i][2]);
                acc[i][3] = fma2(ai, b3, acc[i][3]);
            }
        }
        if (kt < 31) {
            const int nb = 1 - buf;
            As[nb][ak4 + 0][ar] = la0.x; As[nb][ak4 + 1][ar] = la0.y;
            As[nb][ak4 + 2][ar] = la0.z; As[nb][ak4 + 3][ar] = la0.w;
            As[nb][ak4 + 4][ar] = la1.x; As[nb][ak4 + 5][ar] = la1.y;
            As[nb][ak4 + 6][ar] = la1.z; As[nb][ak4 + 7][ar] = la1.w;
            *(float4*)&Bs[nb][bk][bn]     = lb0;
            *(float4*)&Bs[nb][bk][bn + 4] = lb1;
        }
        __syncthreads();
    }

    #pragma unroll
    for (int j = 0; j < 4; ++j) {
        const int col = n0 + 2 * tx + 32 * j;
        float2 bb = *(const float2*)&bias[col];
        #pragma unroll
        for (int i = 0; i < 8; ++i) {
            float o0, o1; upk2(acc[i][j], o0, o1);
            *(float2*)&C[(m0 + ty * 8 + i) * 512 + col] =
                make_float2(o0 + bb.x, o1 + bb.y);
        }
    }
}

__global__ __launch_bounds__(256, 2) void sgemm_big3(
    const float* __restrict__ Aq, const float2* __restrict__ Sq, const float* __restrict__ W1q, const float* __restrict__ B1q, const float* __restrict__ Wq, const float* __restrict__ Bq, float* __restrict__ Cq,
    const float* __restrict__ Ak, const float2* __restrict__ Sk, const float* __restrict__ W1k, const float* __restrict__ B1k, const float* __restrict__ Wk, const float* __restrict__ Bk, float* __restrict__ Ck,
    const float* __restrict__ Av, const float2* __restrict__ Sv, const float* __restrict__ W1v, const float* __restrict__ B1v, const float* __restrict__ Wv, const float* __restrict__ Bv, float* __restrict__ Cv)
{
    const int bx = blockIdx.x;
    const int n0 = blockIdx.y * 128;
    if (bx < 8)
        sgemm_big_body_ln(Aq, Sq, W1q, B1q, Wq, Bq, Cq, (size_t)bx * 128, n0);
    else if (bx < 72)
        sgemm_big_body_ln(Ak, Sk, W1k, B1k, Wk, Bk, Ck, (size_t)(bx - 8) * 128, n0);
    else
        sgemm_big_body_ln(Av, Sv, W1v, B1v, Wv, Bv, Cv, (size_t)(bx - 72) * 128, n0);
}

// ---------------------------------------------------------------------------
// Tail GEMM, 2-way split-K with atomic accumulation into pre-zeroed C.
// 32x128 tile, 256 threads, 2x8 thread tile, optional fused LN.
// grid (M/32, 4, 2); blockIdx.z = K half. Split 0 adds bias.
// ---------------------------------------------------------------------------
__global__ __launch_bounds__(256) void sgemm_tail(
    const float* __restrict__ A, const float* __restrict__ B,
    const float* __restrict__ bias, float* __restrict__ C,
    const float2* __restrict__ stats, const float* __restrict__ lnw,
    const float* __restrict__ lnb, int do_ln)
{
    __shared__ float As[2][16][36];
    __shared__ float Bs[2][16][132];

    const int tid = threadIdx.x;
    const int ty = tid >> 4;
    const int tx = tid & 15;
    const size_t m0 = (size_t)blockIdx.x * 32;
    const int n0 = blockIdx.y * 128;
    const int kbase = blockIdx.z * 256;

    const int ar  = tid >> 2;
    const int ak4 = (tid & 3) * 4;
    const int bk  = tid >> 4;
    const int bn  = (tid & 15) * 8;
    const bool aload = tid < 128;

    float2 st = make_float2(0.f, 1.f);
    if (do_ln && aload) st = stats[m0 + ar];

    u64 acc[2][4];
    #pragma unroll
    for (int i = 0; i < 2; ++i)
        #pragma unroll
        for (int j = 0; j < 4; ++j) acc[i][j] = 0ull;

    float4 la = make_float4(0, 0, 0, 0);
    float4 lb0, lb1;
    if (aload) {
        float4 r = *(const float4*)&A[(m0 + ar) * 512 + kbase + ak4];
        if (do_ln) {
            float4 w = *(const float4*)&lnw[kbase + ak4];
            float4 b = *(const float4*)&lnb[kbase + ak4];
            la.x = (r.x - st.x) * st.y * w.x + b.x;
            la.y = (r.y - st.x) * st.y * w.y + b.y;
            la.z = (r.z - st.x) * st.y * w.z + b.z;
            la.w = (r.w - st.x) * st.y * w.w + b.w;
        } else la = r;
    }
    lb0 = *(const float4*)&B[(size_t)(kbase + bk) * 512 + n0 + bn];
    lb1 = *(const float4*)&B[(size_t)(kbase + bk) * 512 + n0 + bn + 4];
    if (aload) {
        As[0][ak4 + 0][ar] = la.x; As[0][ak4 + 1][ar] = la.y;
        As[0][ak4 + 2][ar] = la.z; As[0][ak4 + 3][ar] = la.w;
    }
    *(float4*)&Bs[0][bk][bn]     = lb0;
    *(float4*)&Bs[0][bk][bn + 4] = lb1;
    __syncthreads();

    for (int kt = 0; kt < 16; ++kt) {
        const int buf = kt & 1;
        if (kt < 15) {
            const int k0 = kbase + (kt + 1) * 16;
            if (aload) {
                float4 r = *(const float4*)&A[(m0 + ar) * 512 + k0 + ak4];
                if (do_ln) {
                    float4 w = *(const float4*)&lnw[k0 + ak4];
                    float4 b = *(const float4*)&lnb[k0 + ak4];
                    la.x = (r.x - st.x) * st.y * w.x + b.x;
                    la.y = (r.y - st.x) * st.y * w.y + b.y;
                    la.z = (r.z - st.x) * st.y * w.z + b.z;
                    la.w = (r.w - st.x) * st.y * w.w + b.w;
                } else la = r;
            }
            lb0 = *(const float4*)&B[(size_t)(k0 + bk) * 512 + n0 + bn];
            lb1 = *(const float4*)&B[(size_t)(k0 + bk) * 512 + n0 + bn + 4];
        }
        #pragma unroll
        for (int kk = 0; kk < 16; ++kk) {
            float2 a = *(const float2*)&As[buf][kk][ty * 2];
            u64 b0 = *(const u64*)&Bs[buf][kk][2 * tx];
            u64 b1 = *(const u64*)&Bs[buf][kk][2 * tx + 32];
            u64 b2 = *(const u64*)&Bs[buf][kk][2 * tx + 64];
            u64 b3 = *(const u64*)&Bs[buf][kk][2 * tx + 96];
            u64 a0 = pk2(a.x, a.x), a1 = pk2(a.y, a.y);
            acc[0][0] = fma2(a0, b0, acc[0][0]);
            acc[0][1] = fma2(a0, b1, acc[0][1]);
            acc[0][2] = fma2(a0, b2, acc[0][2]);
            acc[0][3] = fma2(a0, b3, acc[0][3]);
            acc[1][0] = fma2(a1, b0, acc[1][0]);
            acc[1][1] = fma2(a1, b1, acc[1][1]);
            acc[1][2] = fma2(a1, b2, acc[1][2]);
            acc[1][3] = fma2(a1, b3, acc[1][3]);
        }
        if (kt < 15) {
            const int nb = 1 - buf;
            if (aload) {
                As[nb][ak4 + 0][ar] = la.x; As[nb][ak4 + 1][ar] = la.y;
                As[nb][ak4 + 2][ar] = la.z; As[nb][ak4 + 3][ar] = la.w;
            }
            *(float4*)&Bs[nb][bk][bn]     = lb0;
            *(float4*)&Bs[nb][bk][bn + 4] = lb1;
        }
        __syncthreads();
    }

    const bool addb = (blockIdx.z == 0);
    #pragma unroll
    for (int j = 0; j < 4; ++j) {
        const int col = n0 + 2 * tx + 32 * j;
        float2 bb = addb ? *(const float2*)&bias[col] : make_float2(0.f, 0.f);
        #pragma unroll
        for (int i = 0; i < 2; ++i) {
            float o0, o1; upk2(acc[i][j], o0, o1);
            float* cp = &C[(m0 + ty * 2 + i) * 512 + col];
            atomicAdd(cp,     o0 + bb.x);
            atomicAdd(cp + 1, o1 + bb.y);
        }
    }
}

// ---------------------------------------------------------------------------
// Fused ColBERT attention. Block 256 thr / 8 warps, grid (16, 8).
// 64-token tile, 8 rows/warp (lane = cc), 64 chunks of 32 contexts.
// Per-lane partial softmax denominators (NO per-chunk sum shfl — the 5-deep
// shfl-sum chain is replaced by 1 FFMA/row; one reduce at the end).
// p stored duplicated (stride-20, conflict-free), Q pre-scaled by 1/8.
// smem floats: qs[4096] | ks 2x[8192] | vs 2x[2048] | pd[8*32*20] = 29696
// ---------------------------------------------------------------------------
#define ATT_SMEM (29696 * 4)

__global__ __launch_bounds__(256) void attn_kernel(
    const float* __restrict__ q, const float* __restrict__ k,
    const float* __restrict__ v, float* __restrict__ outp)
{
    extern __shared__ float sm[];
    float* qs  = sm;             // [64][64], pre-scaled by 0.125
    float* ksb = sm + 4096;      // 2 x [u][cc][64] swizzled
    float* vsb = sm + 20480;     // 2 x [cc][64]
    float* pd  = sm + 24576;     // [warp][cc][20] duplicated p pairs

    const int tid  = threadIdx.x;
    const int w    = tid >> 5;
    const int lane = tid & 31;
    const int h    = blockIdx.y;
    const int bt0  = blockIdx.x * 64;
    const int r0   = w * 8;
    const int sw   = (lane & 7) << 2;
    const uint32_t smb = smem_u32(sm);

    const int scc = tid >> 3, srr = tid & 7;
    const float* kg = k + ((size_t)scc * 4) * 512 + h * 64 + srr * 4;
    const uint32_t koff0 = (uint32_t)(scc * 64 + ((srr * 4) ^ ((scc & 7) << 2)));
    const float* vg = v + (size_t)(tid >> 4) * 512 + h * 64 + (tid & 15) * 4;
    const uint32_t voff0 = (uint32_t)((tid >> 4) * 64 + (tid & 15) * 4);

    // Q staging with 1/8 scale folded in: 1024 float4
    #pragma unroll
    for (int j = 0; j < 4; ++j) {
        int i = tid + 256 * j;
        int dd = i & 15, r = i >> 4;
        float4 t = *(const float4*)&q[(size_t)(bt0 + r) * 512 + h * 64 + dd * 4];
        *(float4*)&qs[r * 64 + dd * 4] =
            make_float4(t.x * 0.125f, t.y * 0.125f, t.z * 0.125f, t.w * 0.125f);
    }

    auto stage = [&](int b, int c) {
        const float* kp = kg + (size_t)c * 65536;
        const uint32_t kd = smb + (4096 + b * 8192 + koff0) * 4;
        #pragma unroll
        for (int j = 0; j < 8; ++j)
            CP_ASYNC16(kd + (uint32_t)(((j & 1) * 32 + (j >> 1) * 2048) * 4),
                       kp + (j >> 1) * 512 + (j & 1) * 32);
        const float* vp = vg + (size_t)c * 16384;
        const uint32_t vd = smb + (20480 + b * 2048 + voff0) * 4;
        CP_ASYNC16(vd, vp);
        CP_ASYNC16(vd + 1024 * 4, vp + 8192);
    };

    stage(0, 0); CP_COMMIT();

    float m[8], lp[8];          // lp = PER-LANE partial denominator
    u64 o2[8];
    #pragma unroll
    for (int r = 0; r < 8; ++r) { m[r] = -1e30f; lp[r] = 0.f; o2[r] = 0ull; }

    float* pw = pd + w * 640;    // 32 cc x 20 floats

    for (int c = 0; c < 64; ++c) {
        const int buf = c & 1;
        if (c < 63) { stage(buf ^ 1, c + 1); CP_COMMIT(); CP_WAIT(1); }
        else        { CP_WAIT(0); }
        __syncthreads();

        const float* ks = ksb + buf * 8192;
        const float* vs = vsb + buf * 2048;
        const float* kb = ks + lane * 64;

        // ---- scores: acc[r][u], 8 rows x 4 u per warp
        u64 acc[8][4];
        #pragma unroll
        for (int r = 0; r < 8; ++r)
            #pragma unroll
            for (int u = 0; u < 4; ++u) acc[r][u] = 0ull;

        #pragma unroll
        for (int d4 = 0; d4 < 64; d4 += 4) {
            const int off = d4 ^ sw;
            ulonglong2 k0 = *(const ulonglong2*)&kb[off];
            ulonglong2 k1 = *(const ulonglong2*)&kb[off + 2048];
            ulonglong2 k2 = *(const ulonglong2*)&kb[off + 4096];
            ulonglong2 k3 = *(const ulonglong2*)&kb[off + 6144];
            #pragma unroll
            for (int r = 0; r < 8; ++r) {
                ulonglong2 qq = *(const ulonglong2*)&qs[(r0 + r) * 64 + d4];
                acc[r][0] = fma2(qq.x, k0.x, acc[r][0]);
                acc[r][0] = fma2(qq.y, k0.y, acc[r][0]);
                acc[r][1] = fma2(qq.x, k1.x, acc[r][1]);
                acc[r][1] = fma2(qq.y, k1.y, acc[r][1]);
                acc[r][2] = fma2(qq.x, k2.x, acc[r][2]);
                acc[r][2] = fma2(qq.y, k2.y, acc[r][2]);
                acc[r][3] = fma2(qq.x, k3.x, acc[r][3]);
                acc[r][3] = fma2(qq.y, k3.y, acc[r][3]);
            }
        }

        // ---- MaxSim + online softmax (max shfl only; l kept per-lane)
        float pv[8];
        #pragma unroll
        for (int r = 0; r < 8; ++r) {
            float x0, x1, s;
            upk2(acc[r][0], x0, x1); s = x0 + x1;
            upk2(acc[r][1], x0, x1); s = fmaxf(s, x0 + x1);
            upk2(acc[r][2], x0, x1); s = fmaxf(s, x0 + x1);
            upk2(acc[r][3], x0, x1); s = fmaxf(s, x0 + x1);
            float cm = s;
            #pragma unroll
            for (int o = 16; o; o >>= 1)
                cm = fmaxf(cm, __shfl_xor_sync(0xffffffffu, cm, o));
            float mn   = fmaxf(m[r], cm);
            float corr = __expf(m[r] - mn);
            pv[r] = __expf(s - mn);
            lp[r] = lp[r] * corr + pv[r];
            m[r] = mn;
            o2[r] = mul2(o2[r], pk2(corr, corr));
        }

        // store duplicated p: pd[w][cc][2r],[2r+1] = p[r]; stride 20 floats
        {
            float* pp = &pw[lane * 20];
            *(float4*)&pp[0]  = make_float4(pv[0], pv[0], pv[1], pv[1]);
            *(float4*)&pp[4]  = make_float4(pv[2], pv[2], pv[3], pv[3]);
            *(float4*)&pp[8]  = make_float4(pv[4], pv[4], pv[5], pv[5]);
            *(float4*)&pp[12] = make_float4(pv[6], pv[6], pv[7], pv[7]);
        }
        __syncwarp();

        // ---- AV: o[r][2lane..] += p[r][j] * v[j][2lane..]
        #pragma unroll 4
        for (int j = 0; j < 32; ++j) {
            u64 vj = *(const u64*)&vs[j * 64 + 2 * lane];
            const float* pp = &pw[j * 20];
            ulonglong2 pA = *(const ulonglong2*)&pp[0];
            ulonglong2 pB = *(const ulonglong2*)&pp[4];
            ulonglong2 pC = *(const ulonglong2*)&pp[8];
            ulonglong2 pD = *(const ulonglong2*)&pp[12];
            o2[0] = fma2(pA.x, vj, o2[0]);
            o2[1] = fma2(pA.y, vj, o2[1]);
            o2[2] = fma2(pB.x, vj, o2[2]);
            o2[3] = fma2(pB.y, vj, o2[3]);
            o2[4] = fma2(pC.x, vj, o2[4]);
            o2[5] = fma2(pC.y, vj, o2[5]);
            o2[6] = fma2(pD.x, vj, o2[6]);
            o2[7] = fma2(pD.y, vj, o2[7]);
        }
        __syncwarp();
        __syncthreads();
    }

    // ---- final l reduce (once) + normalize + write
    #pragma unroll
    for (int r = 0; r < 8; ++r) {
        float ls = lp[r];
        #pragma unroll
        for (int o = 16; o; o >>= 1)
            ls += __shfl_xor_sync(0xffffffffu, ls, o);
        float inv = 1.f / ls;
        float lo, hi; upk2(o2[r], lo, hi);
        *(float2*)&outp[(size_t)(bt0 + r0 + r) * 512 + h * 64 + 2 * lane] =
            make_float2(lo * inv, hi * inv);
    }
}

// ---------------------------------------------------------------------------
extern "C" void kernel_launch(void* const* d_in, const int* in_sizes, int n_in,
                              void* d_out, int out_size)
{
    const float* model_embed = (const float*)d_in[0];
    const float* ctx_key     = (const float*)d_in[1];
    const float* ctx_val     = (const float*)d_in[2];
    const float* ln1w = (const float*)d_in[3];
    const float* ln1b = (const float*)d_in[4];
    const float* ln2w = (const float*)d_in[5];
    const float* ln2b = (const float*)d_in[6];
    const float* ln3w = (const float*)d_in[7];
    const float* ln3b = (const float*)d_in[8];
    const float* ln4w = (const float*)d_in[9];
    const float* ln4b = (const float*)d_in[10];
    const float* wq = (const float*)d_in[11];
    const float* bq = (const float*)d_in[12];
    const float* wk = (const float*)d_in[13];
    const float* bk = (const float*)d_in[14];
    const float* wv = (const float*)d_in[15];
    const float* bv = (const float*)d_in[16];
    const float* wo = (const float*)d_in[17];
    const float* bo = (const float*)d_in[18];
    const float* wp = (const float*)d_in[19];
    const float* bp = (const float*)d_in[20];

    float2 *stats, *stats4;
    float *q, *k, *v, *att, *o;
    cudaGetSymbolAddress((void**)&stats,  g_stats);
    cudaGetSymbolAddress((void**)&stats4, g_stats4);
    cudaGetSymbolAddress((void**)&q,    g_q);
    cudaGetSymbolAddress((void**)&k,    g_k);
    cudaGetSymbolAddress((void**)&v,    g_v);
    cudaGetSymbolAddress((void**)&att,  g_att);
    cudaGetSymbolAddress((void**)&o,    g_o);

    static int attr_set = 0;
    if (!attr_set) {
        cudaFuncSetAttribute(attn_kernel,
                             cudaFuncAttributeMaxDynamicSharedMemorySize, ATT_SMEM);
        attr_set = 1;
    }

    // zero accumulation targets for split-K atomics
    zero2<<<1024, 256>>>(o, (float*)d_out);

    // LN stats + fused LN+GEMM projections
    ln_stats3<<<1408, 256>>>(model_embed, ctx_key, ctx_val, stats);
    sgemm_big3<<<dim3(88, 4), 256>>>(
        model_embed, stats,        ln1w, ln1b, wq, bq, q,
        ctx_key,     stats + 1024, ln2w, ln2b, wk, bk, k,
        ctx_val,     stats + 9216, ln3w, ln3b, wv, bv, v);

    // fused MaxSim attention (64-token tiles, direct output)
    attn_kernel<<<dim3(16, 8), 256, ATT_SMEM>>>(q, k, v, att);

    // output proj (split-K 2x), LN4 stats, final proj (split-K 2x, fused LN)
    sgemm_tail<<<dim3(32, 4, 2), 256>>>(att, wo, bo, o, nullptr, nullptr, nullptr, 0);
    ln_stats1<<<128, 256>>>(o, stats4);
    sgemm_tail<<<dim3(32, 4, 2), 256>>>(o, wp, bp, (float*)d_out, stats4, ln4w, ln4b, 1);
}

// round 12
// speedup vs baseline: 1.0171x; 1.0171x over previous
#include <cuda_runtime.h>
#include <cstdint>
#include <math.h>

// Shapes fixed: B=4, T=256, C=2048, U=4, D=512, P=512, H=8, dk=64

__device__ float2 g_stats[11264];   // mu/rstd for q(1024)|k(8192)|v(2048) rows
__device__ float2 g_stats4[1024];   // mu/rstd for LN4
__device__ float g_q  [1024 * 512];
__device__ float g_k  [8192 * 512];
__device__ float g_v  [2048 * 512];
__device__ float g_att[1024 * 512];
__device__ float g_o  [1024 * 512];

typedef unsigned long long u64;

__device__ __forceinline__ u64 pk2(float lo, float hi) {
    u64 r; asm("mov.b64 %0, {%1, %2};" : "=l"(r) : "f"(lo), "f"(hi)); return r;
}
__device__ __forceinline__ void upk2(u64 v, float& lo, float& hi) {
    asm("mov.b64 {%0, %1}, %2;" : "=f"(lo), "=f"(hi) : "l"(v));
}
__device__ __forceinline__ u64 fma2(u64 a, u64 b, u64 c) {
    u64 d; asm("fma.rn.f32x2 %0, %1, %2, %3;" : "=l"(d) : "l"(a), "l"(b), "l"(c)); return d;
}
__device__ __forceinline__ u64 mul2(u64 a, u64 b) {
    u64 d; asm("mul.rn.f32x2 %0, %1, %2;" : "=l"(d) : "l"(a), "l"(b)); return d;
}
__device__ __forceinline__ uint32_t smem_u32(const void* p) {
    uint32_t a;
    asm("{ .reg .u64 t; cvta.to.shared.u64 t, %1; cvt.u32.u64 %0, t; }" : "=r"(a) : "l"(p));
    return a;
}
#define CP_ASYNC16(dst, src) \
    asm volatile("cp.async.cg.shared.global [%0], [%1], 16;" :: "r"(dst), "l"(src) : "memory")
#define CP_COMMIT() asm volatile("cp.async.commit_group;" ::: "memory")
#define CP_WAIT(n)  asm volatile("cp.async.wait_group %0;" :: "n"(n) : "memory")

// ---------------------------------------------------------------------------
// LN stats: one warp per row, D=512. Writes (mu, rstd).
// ---------------------------------------------------------------------------
__device__ __forceinline__ void ln_stat_row(
    const float* __restrict__ xr, float2* __restrict__ out, int lane)
{
    float s = 0.f, ss = 0.f;
    #pragma unroll
    for (int j = 0; j < 4; ++j) {
        float4 x = *(const float4*)&xr[j * 128 + lane * 4];
        s  += x.x + x.y + x.z + x.w;
        ss += x.x * x.x + x.y * x.y + x.z * x.z + x.w * x.w;
    }
    #pragma unroll
    for (int o = 16; o; o >>= 1) {
        s  += __shfl_xor_sync(0xffffffffu, s, o);
        ss += __shfl_xor_sync(0xffffffffu, ss, o);
    }
    if (lane == 0) {
        float mu = s * (1.f / 512.f);
        float rstd = rsqrtf(ss * (1.f / 512.f) - mu * mu + 1e-5f);
        *out = make_float2(mu, rstd);
    }
}

__global__ __launch_bounds__(256) void ln_stats3(
    const float* __restrict__ x0, const float* __restrict__ x1,
    const float* __restrict__ x2, float2* __restrict__ st)
{
    const int lane = threadIdx.x & 31;
    const int wr = threadIdx.x >> 5;
    const int bx = blockIdx.x;
    const float* x; size_t row; float2* o;
    if (bx < 128)       { x = x0; row = (size_t)bx * 8 + wr; o = st; }
    else if (bx < 1152) { x = x1; row = (size_t)(bx - 128) * 8 + wr; o = st + 1024; }
    else                { x = x2; row = (size_t)(bx - 1152) * 8 + wr; o = st + 9216; }
    ln_stat_row(x + row * 512, o + row, lane);
}

__global__ __launch_bounds__(256) void ln_stats1(
    const float* __restrict__ x, float2* __restrict__ st)
{
    const int lane = threadIdx.x & 31;
    const size_t row = (size_t)blockIdx.x * 8 + (threadIdx.x >> 5);
    ln_stat_row(x + row * 512, st + row, lane);
}

// ---------------------------------------------------------------------------
// sgemm_big with fused LN on A-load: 128x128 tile, BK=16, 256 thr, 8x8 tile.
// (R7 configuration: no register cap.)
// ---------------------------------------------------------------------------
__device__ __forceinline__ void sgemm_big_body_ln(
    const float* __restrict__ A, const float2* __restrict__ stats,
    const float* __restrict__ lnw, const float* __restrict__ lnb,
    const float* __restrict__ B, const float* __restrict__ bias,
    float* __restrict__ C, size_t m0, int n0)
{
    __shared__ float As[2][16][132];
    __shared__ float Bs[2][16][132];

    const int tid = threadIdx.x;
    const int ty = tid >> 4, tx = tid & 15;
    const int ar = tid >> 1, ak4 = (tid & 1) * 8;
    const int bk = tid >> 4, bn = (tid & 15) * 8;

    const float2 st = stats[m0 + ar];

    u64 acc[8][4];
    #pragma unroll
    for (int i = 0; i < 8; ++i)
        #pragma unroll
        for (int j = 0; j < 4; ++j) acc[i][j] = 0ull;

    float4 la0, la1, lb0, lb1;
    {
        float4 r0 = *(const float4*)&A[(m0 + ar) * 512 + ak4];
        float4 r1 = *(const float4*)&A[(m0 + ar) * 512 + ak4 + 4];
        float4 w0 = *(const float4*)&lnw[ak4];
        float4 w1 = *(const float4*)&lnw[ak4 + 4];
        float4 b0 = *(const float4*)&lnb[ak4];
        float4 b1 = *(const float4*)&lnb[ak4 + 4];
        la0.x = (r0.x - st.x) * st.y * w0.x + b0.x;
        la0.y = (r0.y - st.x) * st.y * w0.y + b0.y;
        la0.z = (r0.z - st.x) * st.y * w0.z + b0.z;
        la0.w = (r0.w - st.x) * st.y * w0.w + b0.w;
        la1.x = (r1.x - st.x) * st.y * w1.x + b1.x;
        la1.y = (r1.y - st.x) * st.y * w1.y + b1.y;
        la1.z = (r1.z - st.x) * st.y * w1.z + b1.z;
        la1.w = (r1.w - st.x) * st.y * w1.w + b1.w;
    }
    lb0 = *(const float4*)&B[(size_t)bk * 512 + n0 + bn];
    lb1 = *(const float4*)&B[(size_t)bk * 512 + n0 + bn + 4];
    {
        As[0][ak4 + 0][ar] = la0.x; As[0][ak4 + 1][ar] = la0.y;
        As[0][ak4 + 2][ar] = la0.z; As[0][ak4 + 3][ar] = la0.w;
        As[0][ak4 + 4][ar] = la1.x; As[0][ak4 + 5][ar] = la1.y;
        As[0][ak4 + 6][ar] = la1.z; As[0][ak4 + 7][ar] = la1.w;
        *(float4*)&Bs[0][bk][bn]     = lb0;
        *(float4*)&Bs[0][bk][bn + 4] = lb1;
    }
    __syncthreads();

    for (int kt = 0; kt < 32; ++kt) {
        const int buf = kt & 1;
        if (kt < 31) {
            const int k0 = (kt + 1) * 16;
            float4 r0 = *(const float4*)&A[(m0 + ar) * 512 + k0 + ak4];
            float4 r1 = *(const float4*)&A[(m0 + ar) * 512 + k0 + ak4 + 4];
            float4 w0 = *(const float4*)&lnw[k0 + ak4];
            float4 w1 = *(const float4*)&lnw[k0 + ak4 + 4];
            float4 b0 = *(const float4*)&lnb[k0 + ak4];
            float4 b1 = *(const float4*)&lnb[k0 + ak4 + 4];
            la0.x = (r0.x - st.x) * st.y * w0.x + b0.x;
            la0.y = (r0.y - st.x) * st.y * w0.y + b0.y;
            la0.z = (r0.z - st.x) * st.y * w0.z + b0.z;
            la0.w = (r0.w - st.x) * st.y * w0.w + b0.w;
            la1.x = (r1.x - st.x) * st.y * w1.x + b1.x;
            la1.y = (r1.y - st.x) * st.y * w1.y + b1.y;
            la1.z = (r1.z - st.x) * st.y * w1.z + b1.z;
            la1.w = (r1.w - st.x) * st.y * w1.w + b1.w;
            lb0 = *(const float4*)&B[(size_t)(k0 + bk) * 512 + n0 + bn];
            lb1 = *(const float4*)&B[(size_t)(k0 + bk) * 512 + n0 + bn + 4];
        }
        #pragma unroll
        for (int kk = 0; kk < 16; ++kk) {
            float4 a0 = *(const float4*)&As[buf][kk][ty * 8];
            float4 a1 = *(const float4*)&As[buf][kk][ty * 8 + 4];
            u64 b0 = *(const u64*)&Bs[buf][kk][2 * tx];
            u64 b1 = *(const u64*)&Bs[buf][kk][2 * tx + 32];
            u64 b2 = *(const u64*)&Bs[buf][kk][2 * tx + 64];
            u64 b3 = *(const u64*)&Bs[buf][kk][2 * tx + 96];
            float av[8] = {a0.x, a0.y, a0.z, a0.w, a1.x, a1.y, a1.z, a1.w};
            #pragma unroll
            for (int i = 0; i < 8; ++i) {
                u64 ai = pk2(av[i], av[i]);
                acc[i][0] = fma2(ai, b0, acc[i][0]);
                acc[i][1] = fma2(ai, b1, acc[i][1]);
                acc[i][2] = fma2(ai, b2, acc[i][2]);
                acc[i][3] = fma2(ai, b3, acc[i][3]);
            }
        }
        if (kt < 31) {
            const int nb = 1 - buf;
            As[nb][ak4 + 0][ar] = la0.x; As[nb][ak4 + 1][ar] = la0.y;
            As[nb][ak4 + 2][ar] = la0.z; As[nb][ak4 + 3][ar] = la0.w;
            As[nb][ak4 + 4][ar] = la1.x; As[nb][ak4 + 5][ar] = la1.y;
            As[nb][ak4 + 6][ar] = la1.z; As[nb][ak4 + 7][ar] = la1.w;
            *(float4*)&Bs[nb][bk][bn]     = lb0;
            *(float4*)&Bs[nb][bk][bn + 4] = lb1;
        }
        __syncthreads();
    }

    #pragma unroll
    for (int j = 0; j < 4; ++j) {
        const int col = n0 + 2 * tx + 32 * j;
        float2 bb = *(const float2*)&bias[col];
        #pragma unroll
        for (int i = 0; i < 8; ++i) {
            float o0, o1; upk2(acc[i][j], o0, o1);
            *(float2*)&C[(m0 + ty * 8 + i) * 512 + col] =
                make_float2(o0 + bb.x, o1 + bb.y);
        }
    }
}

__global__ __launch_bounds__(256) void sgemm_big3(
    const float* __restrict__ Aq, const float2* __restrict__ Sq, const float* __restrict__ W1q, const float* __restrict__ B1q, const float* __restrict__ Wq, const float* __restrict__ Bq, float* __restrict__ Cq,
    const float* __restrict__ Ak, const float2* __restrict__ Sk, const float* __restrict__ W1k, const float* __restrict__ B1k, const float* __restrict__ Wk, const float* __restrict__ Bk, float* __restrict__ Ck,
    const float* __restrict__ Av, const float2* __restrict__ Sv, const float* __restrict__ W1v, const float* __restrict__ B1v, const float* __restrict__ Wv, const float* __restrict__ Bv, float* __restrict__ Cv)
{
    const int bx = blockIdx.x;
    const int n0 = blockIdx.y * 128;
    if (bx < 8)
        sgemm_big_body_ln(Aq, Sq, W1q, B1q, Wq, Bq, Cq, (size_t)bx * 128, n0);
    else if (bx < 72)
        sgemm_big_body_ln(Ak, Sk, W1k, B1k, Wk, Bk, Ck, (size_t)(bx - 8) * 128, n0);
    else
        sgemm_big_body_ln(Av, Sv, W1v, B1v, Wv, Bv, Cv, (size_t)(bx - 72) * 128, n0);
}

// ---------------------------------------------------------------------------
// Tail GEMM (R7 config): 32x128 tile, BK=16, 256 threads, 2x8 thread tile,
// optional fused LN on A-load. grid (M/32, 4). Full K, direct store.
// ---------------------------------------------------------------------------
__global__ __launch_bounds__(256) void sgemm_tail(
    const float* __restrict__ A, const float* __restrict__ B,
    const float* __restrict__ bias, float* __restrict__ C,
    const float2* __restrict__ stats, const float* __restrict__ lnw,
    const float* __restrict__ lnb, int do_ln)
{
    __shared__ float As[2][16][36];
    __shared__ float Bs[2][16][132];

    const int tid = threadIdx.x;
    const int ty = tid >> 4;
    const int tx = tid & 15;
    const size_t m0 = (size_t)blockIdx.x * 32;
    const int n0 = blockIdx.y * 128;

    const int ar  = tid >> 2;
    const int ak4 = (tid & 3) * 4;
    const int bk  = tid >> 4;
    const int bn  = (tid & 15) * 8;
    const bool aload = tid < 128;

    float2 st = make_float2(0.f, 1.f);
    if (do_ln && aload) st = stats[m0 + ar];

    u64 acc[2][4];
    #pragma unroll
    for (int i = 0; i < 2; ++i)
        #pragma unroll
        for (int j = 0; j < 4; ++j) acc[i][j] = 0ull;

    float4 la = make_float4(0, 0, 0, 0);
    float4 lb0, lb1;
    if (aload) {
        float4 r = *(const float4*)&A[(m0 + ar) * 512 + ak4];
        if (do_ln) {
            float4 w = *(const float4*)&lnw[ak4];
            float4 b = *(const float4*)&lnb[ak4];
            la.x = (r.x - st.x) * st.y * w.x + b.x;
            la.y = (r.y - st.x) * st.y * w.y + b.y;
            la.z = (r.z - st.x) * st.y * w.z + b.z;
            la.w = (r.w - st.x) * st.y * w.w + b.w;
        } else la = r;
    }
    lb0 = *(const float4*)&B[(size_t)bk * 512 + n0 + bn];
    lb1 = *(const float4*)&B[(size_t)bk * 512 + n0 + bn + 4];
    if (aload) {
        As[0][ak4 + 0][ar] = la.x; As[0][ak4 + 1][ar] = la.y;
        As[0][ak4 + 2][ar] = la.z; As[0][ak4 + 3][ar] = la.w;
    }
    *(float4*)&Bs[0][bk][bn]     = lb0;
    *(float4*)&Bs[0][bk][bn + 4] = lb1;
    __syncthreads();

    for (int kt = 0; kt < 32; ++kt) {
        const int buf = kt & 1;
        if (kt < 31) {
            const int k0 = (kt + 1) * 16;
            if (aload) {
                float4 r = *(const float4*)&A[(m0 + ar) * 512 + k0 + ak4];
                if (do_ln) {
                    float4 w = *(const float4*)&lnw[k0 + ak4];
                    float4 b = *(const float4*)&lnb[k0 + ak4];
                    la.x = (r.x - st.x) * st.y * w.x + b.x;
                    la.y = (r.y - st.x) * st.y * w.y + b.y;
                    la.z = (r.z - st.x) * st.y * w.z + b.z;
                    la.w = (r.w - st.x) * st.y * w.w + b.w;
                } else la = r;
            }
            lb0 = *(const float4*)&B[(size_t)(k0 + bk) * 512 + n0 + bn];
            lb1 = *(const float4*)&B[(size_t)(k0 + bk) * 512 + n0 + bn + 4];
        }
        #pragma unroll
        for (int kk = 0; kk < 16; ++kk) {
            float2 a = *(const float2*)&As[buf][kk][ty * 2];
            u64 b0 = *(const u64*)&Bs[buf][kk][2 * tx];
            u64 b1 = *(const u64*)&Bs[buf][kk][2 * tx + 32];
            u64 b2 = *(const u64*)&Bs[buf][kk][2 * tx + 64];
            u64 b3 = *(const u64*)&Bs[buf][kk][2 * tx + 96];
            u64 a0 = pk2(a.x, a.x), a1 = pk2(a.y, a.y);
            acc[0][0] = fma2(a0, b0, acc[0][0]);
            acc[0][1] = fma2(a0, b1, acc[0][1]);
            acc[0][2] = fma2(a0, b2, acc[0][2]);
            acc[0][3] = fma2(a0, b3, acc[0][3]);
            acc[1][0] = fma2(a1, b0, acc[1][0]);
            acc[1][1] = fma2(a1, b1, acc[1][1]);
            acc[1][2] = fma2(a1, b2, acc[1][2]);
            acc[1][3] = fma2(a1, b3, acc[1][3]);
        }
        if (kt < 31) {
            const int nb = 1 - buf;
            if (aload) {
                As[nb][ak4 + 0][ar] = la.x; As[nb][ak4 + 1][ar] = la.y;
                As[nb][ak4 + 2][ar] = la.z; As[nb][ak4 + 3][ar] = la.w;
            }
            *(float4*)&Bs[nb][bk][bn]     = lb0;
            *(float4*)&Bs[nb][bk][bn + 4] = lb1;
        }
        __syncthreads();
    }

    #pragma unroll
    for (int j = 0; j < 4; ++j) {
        const int col = n0 + 2 * tx + 32 * j;
        float2 bb = *(const float2*)&bias[col];
        #pragma unroll
        for (int i = 0; i < 2; ++i) {
            float o0, o1; upk2(acc[i][j], o0, o1);
            *(float2*)&C[(m0 + ty * 2 + i) * 512 + col] =
                make_float2(o0 + bb.x, o1 + bb.y);
        }
    }
}

// ---------------------------------------------------------------------------
// Fused ColBERT attention. Block 256 thr / 8 warps, grid (16, 8).
// 64-token tile, 8 rows/warp (lane = cc), 64 chunks of 32 contexts.
// TRIPLE-buffered cp.async pipeline with ONE barrier per chunk:
//   wait(<=1) -> syncthreads -> compute(c) -> stage(c+2).
// Per-lane partial softmax denominators; duplicated p (stride 20); Q/8.
// smem floats: qs[4096] | ks 3x[8192] | vs 3x[2048] | pd[8*32*20] = 39936
// ---------------------------------------------------------------------------
#define ATT_SMEM (39936 * 4)

__global__ __launch_bounds__(256) void attn_kernel(
    const float* __restrict__ q, const float* __restrict__ k,
    const float* __restrict__ v, float* __restrict__ outp)
{
    extern __shared__ float sm[];
    float* qs  = sm;             // [64][64], pre-scaled by 0.125
    float* ksb = sm + 4096;      // 3 x [u][cc][64] swizzled
    float* vsb = sm + 28672;     // 3 x [cc][64]
    float* pd  = sm + 34816;     // [warp][cc][20] duplicated p pairs

    const int tid  = threadIdx.x;
    const int w    = tid >> 5;
    const int lane = tid & 31;
    const int h    = blockIdx.y;
    const int bt0  = blockIdx.x * 64;
    const int r0   = w * 8;
    const int sw   = (lane & 7) << 2;
    const uint32_t smb = smem_u32(sm);

    const int scc = tid >> 3, srr = tid & 7;
    const float* kg = k + ((size_t)scc * 4) * 512 + h * 64 + srr * 4;
    const uint32_t koff0 = (uint32_t)(scc * 64 + ((srr * 4) ^ ((scc & 7) << 2)));
    const float* vg = v + (size_t)(tid >> 4) * 512 + h * 64 + (tid & 15) * 4;
    const uint32_t voff0 = (uint32_t)((tid >> 4) * 64 + (tid & 15) * 4);

    // Q staging with 1/8 scale folded in: 1024 float4
    #pragma unroll
    for (int j = 0; j < 4; ++j) {
        int i = tid + 256 * j;
        int dd = i & 15, r = i >> 4;
        float4 t = *(const float4*)&q[(size_t)(bt0 + r) * 512 + h * 64 + dd * 4];
        *(float4*)&qs[r * 64 + dd * 4] =
            make_float4(t.x * 0.125f, t.y * 0.125f, t.z * 0.125f, t.w * 0.125f);
    }

    auto stage = [&](int b, int c) {
        const float* kp = kg + (size_t)c * 65536;
        const uint32_t kd = smb + (4096 + b * 8192 + koff0) * 4;
        #pragma unroll
        for (int j = 0; j < 8; ++j)
            CP_ASYNC16(kd + (uint32_t)(((j & 1) * 32 + (j >> 1) * 2048) * 4),
                       kp + (j >> 1) * 512 + (j & 1) * 32);
        const float* vp = vg + (size_t)c * 16384;
        const uint32_t vd = smb + (28672 + b * 2048 + voff0) * 4;
        CP_ASYNC16(vd, vp);
        CP_ASYNC16(vd + 1024 * 4, vp + 8192);
    };

    stage(0, 0); CP_COMMIT();
    stage(1, 1); CP_COMMIT();

    float m[8], lp[8];          // lp = per-lane partial denominator
    u64 o2[8];
    #pragma unroll
    for (int r = 0; r < 8; ++r) { m[r] = -1e30f; lp[r] = 0.f; o2[r] = 0ull; }

    float* pw = pd + w * 640;    // 32 cc x 20 floats

    int buf = 0;                 // buffer of chunk c (cycles 0,1,2,0,..)
    for (int c = 0; c < 64; ++c) {
        if (c < 63) CP_WAIT(1); else CP_WAIT(0);
        __syncthreads();

        const float* ks = ksb + buf * 8192;
        const float* vs = vsb + buf * 2048;
        const float* kb = ks + lane * 64;

        // ---- scores: acc[r][u], 8 rows x 4 u per warp
        u64 acc[8][4];
        #pragma unroll
        for (int r = 0; r < 8; ++r)
            #pragma unroll
            for (int u = 0; u < 4; ++u) acc[r][u] = 0ull;

        #pragma unroll
        for (int d4 = 0; d4 < 64; d4 += 4) {
            const int off = d4 ^ sw;
            ulonglong2 k0 = *(const ulonglong2*)&kb[off];
            ulonglong2 k1 = *(const ulonglong2*)&kb[off + 2048];
            ulonglong2 k2 = *(const ulonglong2*)&kb[off + 4096];
            ulonglong2 k3 = *(const ulonglong2*)&kb[off + 6144];
            #pragma unroll
            for (int r = 0; r < 8; ++r) {
                ulonglong2 qq = *(const ulonglong2*)&qs[(r0 + r) * 64 + d4];
                acc[r][0] = fma2(qq.x, k0.x, acc[r][0]);
                acc[r][0] = fma2(qq.y, k0.y, acc[r][0]);
                acc[r][1] = fma2(qq.x, k1.x, acc[r][1]);
                acc[r][1] = fma2(qq.y, k1.y, acc[r][1]);
                acc[r][2] = fma2(qq.x, k2.x, acc[r][2]);
                acc[r][2] = fma2(qq.y, k2.y, acc[r][2]);
                acc[r][3] = fma2(qq.x, k3.x, acc[r][3]);
                acc[r][3] = fma2(qq.y, k3.y, acc[r][3]);
            }
        }

        // ---- MaxSim + online softmax (max shfl only; l per-lane)
        float pv[8];
        #pragma unroll
        for (int r = 0; r < 8; ++r) {
            float x0, x1, s;
            upk2(acc[r][0], x0, x1); s = x0 + x1;
            upk2(acc[r][1], x0, x1); s = fmaxf(s, x0 + x1);
            upk2(acc[r][2], x0, x1); s = fmaxf(s, x0 + x1);
            upk2(acc[r][3], x0, x1); s = fmaxf(s, x0 + x1);
            float cm = s;
            #pragma unroll
            for (int o = 16; o; o >>= 1)
                cm = fmaxf(cm, __shfl_xor_sync(0xffffffffu, cm, o));
            float mn   = fmaxf(m[r], cm);
            float corr = __expf(m[r] - mn);
            pv[r] = __expf(s - mn);
            lp[r] = lp[r] * corr + pv[r];
            m[r] = mn;
            o2[r] = mul2(o2[r], pk2(corr, corr));
        }

        // store duplicated p: pd[w][cc][2r],[2r+1] = p[r]; stride 20 floats
        {
            float* pp = &pw[lane * 20];
            *(float4*)&pp[0]  = make_float4(pv[0], pv[0], pv[1], pv[1]);
            *(float4*)&pp[4]  = make_float4(pv[2], pv[2], pv[3], pv[3]);
            *(float4*)&pp[8]  = make_float4(pv[4], pv[4], pv[5], pv[5]);
            *(float4*)&pp[12] = make_float4(pv[6], pv[6], pv[7], pv[7]);
        }
        __syncwarp();

        // ---- AV: o[r][2lane..] += p[r][j] * v[j][2lane..]
        #pragma unroll 4
        for (int j = 0; j < 32; ++j) {
            u64 vj = *(const u64*)&vs[j * 64 + 2 * lane];
            const float* pp = &pw[j * 20];
            ulonglong2 pA = *(const ulonglong2*)&pp[0];
            ulonglong2 pB = *(const ulonglong2*)&pp[4];
            ulonglong2 pC = *(const ulonglong2*)&pp[8];
            ulonglong2 pD = *(const ulonglong2*)&pp[12];
            o2[0] = fma2(pA.x, vj, o2[0]);
            o2[1] = fma2(pA.y, vj, o2[1]);
            o2[2] = fma2(pB.x, vj, o2[2]);
            o2[3] = fma2(pB.y, vj, o2[3]);
            o2[4] = fma2(pC.x, vj, o2[4]);
            o2[5] = fma2(pC.y, vj, o2[5]);
            o2[6] = fma2(pD.x, vj, o2[6]);
            o2[7] = fma2(pD.y, vj, o2[7]);
        }
        __syncwarp();

        // ---- prefetch chunk c+2 into the buffer freed by chunk c-1
        if (c < 62) {
            int nb = buf + 2; if (nb >= 3) nb -= 3;
            stage(nb, c + 2);
            CP_COMMIT();
        }
        if (++buf == 3) buf = 0;
    }

    // ---- final l reduce + normalize + write
    #pragma unroll
    for (int r = 0; r < 8; ++r) {
        float ls = lp[r];
        #pragma unroll
        for (int o = 16; o; o >>= 1)
            ls += __shfl_xor_sync(0xffffffffu, ls, o);
        float inv = 1.f / ls;
        float lo, hi; upk2(o2[r], lo, hi);
        *(float2*)&outp[(size_t)(bt0 + r0 + r) * 512 + h * 64 + 2 * lane] =
            make_float2(lo * inv, hi * inv);
    }
}

// ---------------------------------------------------------------------------
extern "C" void kernel_launch(void* const* d_in, const int* in_sizes, int n_in,
                              void* d_out, int out_size)
{
    const float* model_embed = (const float*)d_in[0];
    const float* ctx_key     = (const float*)d_in[1];
    const float* ctx_val     = (const float*)d_in[2];
    const float* ln1w = (const float*)d_in[3];
    const float* ln1b = (const float*)d_in[4];
    const float* ln2w = (const float*)d_in[5];
    const float* ln2b = (const float*)d_in[6];
    const float* ln3w = (const float*)d_in[7];
    const float* ln3b = (const float*)d_in[8];
    const float* ln4w = (const float*)d_in[9];
    const float* ln4b = (const float*)d_in[10];
    const float* wq = (const float*)d_in[11];
    const float* bq = (const float*)d_in[12];
    const float* wk = (const float*)d_in[13];
    const float* bk = (const float*)d_in[14];
    const float* wv = (const float*)d_in[15];
    const float* bv = (const float*)d_in[16];
    const float* wo = (const float*)d_in[17];
    const float* bo = (const float*)d_in[18];
    const float* wp = (const float*)d_in[19];
    const float* bp = (const float*)d_in[20];

    float2 *stats, *stats4;
    float *q, *k, *v, *att, *o;
    cudaGetSymbolAddress((void**)&stats,  g_stats);
    cudaGetSymbolAddress((void**)&stats4, g_stats4);
    cudaGetSymbolAddress((void**)&q,    g_q);
    cudaGetSymbolAddress((void**)&k,    g_k);
    cudaGetSymbolAddress((void**)&v,    g_v);
    cudaGetSymbolAddress((void**)&att,  g_att);
    cudaGetSymbolAddress((void**)&o,    g_o);

    static int attr_set = 0;
    if (!attr_set) {
        cudaFuncSetAttribute(attn_kernel,
                             cudaFuncAttributeMaxDynamicSharedMemorySize, ATT_SMEM);
        attr_set = 1;
    }

    // LN stats + fused LN+GEMM projections
    ln_stats3<<<1408, 256>>>(model_embed, ctx_key, ctx_val, stats);
    sgemm_big3<<<dim3(88, 4), 256>>>(
        model_embed, stats,        ln1w, ln1b, wq, bq, q,
        ctx_key,     stats + 1024, ln2w, ln2b, wk, bk, k,
        ctx_val,     stats + 9216, ln3w, ln3b, wv, bv, v);

    // fused MaxSim attention (64-token tiles, triple-buffered pipeline)
    attn_kernel<<<dim3(16, 8), 256, ATT_SMEM>>>(q, k, v, att);

    // output proj, LN4 stats, final proj (fused LN)
    sgemm_tail<<<dim3(32, 4), 256>>>(att, wo, bo, o, nullptr, nullptr, nullptr, 0);
    ln_stats1<<<128, 256>>>(o, stats4);
    sgemm_tail<<<dim3(32, 4), 256>>>(o, wp, bp, (float*)d_out, stats4, ln4w, ln4b, 1);
}

// round 13
// speedup vs baseline: 1.0843x; 1.0660x over previous
#include <cuda_runtime.h>
#include <cstdint>
#include <math.h>

// Shapes fixed: B=4, T=256, C=2048, U=4, D=512, P=512, H=8, dk=64

__device__ float2 g_stats[11264];   // mu/rstd for q(1024)|k(8192)|v(2048) rows
__device__ float2 g_stats4[1024];   // mu/rstd for LN4
__device__ float g_q  [1024 * 512];
__device__ float g_k  [8192 * 512];
__device__ float g_v  [2048 * 512];
__device__ float g_att[1024 * 512];
__device__ float g_o  [1024 * 512];

typedef unsigned long long u64;

__device__ __forceinline__ u64 pk2(float lo, float hi) {
    u64 r; asm("mov.b64 %0, {%1, %2};" : "=l"(r) : "f"(lo), "f"(hi)); return r;
}
__device__ __forceinline__ void upk2(u64 v, float& lo, float& hi) {
    asm("mov.b64 {%0, %1}, %2;" : "=f"(lo), "=f"(hi) : "l"(v));
}
__device__ __forceinline__ u64 fma2(u64 a, u64 b, u64 c) {
    u64 d; asm("fma.rn.f32x2 %0, %1, %2, %3;" : "=l"(d) : "l"(a), "l"(b), "l"(c)); return d;
}
__device__ __forceinline__ u64 mul2(u64 a, u64 b) {
    u64 d; asm("mul.rn.f32x2 %0, %1, %2;" : "=l"(d) : "l"(a), "l"(b)); return d;
}
__device__ __forceinline__ uint32_t smem_u32(const void* p) {
    uint32_t a;
    asm("{ .reg .u64 t; cvta.to.shared.u64 t, %1; cvt.u32.u64 %0, t; }" : "=r"(a) : "l"(p));
    return a;
}
#define CP_ASYNC16(dst, src) \
    asm volatile("cp.async.cg.shared.global [%0], [%1], 16;" :: "r"(dst), "l"(src) : "memory")
#define CP_COMMIT() asm volatile("cp.async.commit_group;" ::: "memory")
#define CP_WAIT(n)  asm volatile("cp.async.wait_group %0;" :: "n"(n) : "memory")

// ---------------------------------------------------------------------------
// zero both atomic-accumulation targets (g_o, d_out): 2 x 524288 floats.
// ---------------------------------------------------------------------------
__global__ __launch_bounds__(256) void zero2(float* __restrict__ a, float* __restrict__ b)
{
    int i = blockIdx.x * 256 + threadIdx.x;
    if (i < 131072) *(float4*)&a[i * 4] = make_float4(0.f, 0.f, 0.f, 0.f);
    else { i -= 131072; *(float4*)&b[i * 4] = make_float4(0.f, 0.f, 0.f, 0.f); }
}

// ---------------------------------------------------------------------------
// LN stats: one warp per row, D=512. Writes (mu, rstd).
// ---------------------------------------------------------------------------
__device__ __forceinline__ void ln_stat_row(
    const float* __restrict__ xr, float2* __restrict__ out, int lane)
{
    float s = 0.f, ss = 0.f;
    #pragma unroll
    for (int j = 0; j < 4; ++j) {
        float4 x = *(const float4*)&xr[j * 128 + lane * 4];
        s  += x.x + x.y + x.z + x.w;
        ss += x.x * x.x + x.y * x.y + x.z * x.z + x.w * x.w;
    }
    #pragma unroll
    for (int o = 16; o; o >>= 1) {
        s  += __shfl_xor_sync(0xffffffffu, s, o);
        ss += __shfl_xor_sync(0xffffffffu, ss, o);
    }
    if (lane == 0) {
        float mu = s * (1.f / 512.f);
        float rstd = rsqrtf(ss * (1.f / 512.f) - mu * mu + 1e-5f);
        *out = make_float2(mu, rstd);
    }
}

__global__ __launch_bounds__(256) void ln_stats3(
    const float* __restrict__ x0, const float* __restrict__ x1,
    const float* __restrict__ x2, float2* __restrict__ st)
{
    const int lane = threadIdx.x & 31;
    const int wr = threadIdx.x >> 5;
    const int bx = blockIdx.x;
    const float* x; size_t row; float2* o;
    if (bx < 128)       { x = x0; row = (size_t)bx * 8 + wr; o = st; }
    else if (bx < 1152) { x = x1; row = (size_t)(bx - 128) * 8 + wr; o = st + 1024; }
    else                { x = x2; row = (size_t)(bx - 1152) * 8 + wr; o = st + 9216; }
    ln_stat_row(x + row * 512, o + row, lane);
}

__global__ __launch_bounds__(256) void ln_stats1(
    const float* __restrict__ x, float2* __restrict__ st)
{
    const int lane = threadIdx.x & 31;
    const size_t row = (size_t)blockIdx.x * 8 + (threadIdx.x >> 5);
    ln_stat_row(x + row * 512, st + row, lane);
}

// ---------------------------------------------------------------------------
// sgemm_big with fused LN on A-load: 128x128 tile, BK=16, 256 thr, 8x8 tile.
// (R7 configuration: no register cap.)
// ---------------------------------------------------------------------------
__device__ __forceinline__ void sgemm_big_body_ln(
    const float* __restrict__ A, const float2* __restrict__ stats,
    const float* __restrict__ lnw, const float* __restrict__ lnb,
    const float* __restrict__ B, const float* __restrict__ bias,
    float* __restrict__ C, size_t m0, int n0)
{
    __shared__ float As[2][16][132];
    __shared__ float Bs[2][16][132];

    const int tid = threadIdx.x;
    const int ty = tid >> 4, tx = tid & 15;
    const int ar = tid >> 1, ak4 = (tid & 1) * 8;
    const int bk = tid >> 4, bn = (tid & 15) * 8;

    const float2 st = stats[m0 + ar];

    u64 acc[8][4];
    #pragma unroll
    for (int i = 0; i < 8; ++i)
        #pragma unroll
        for (int j = 0; j < 4; ++j) acc[i][j] = 0ull;

    float4 la0, la1, lb0, lb1;
    {
        float4 r0 = *(const float4*)&A[(m0 + ar) * 512 + ak4];
        float4 r1 = *(const float4*)&A[(m0 + ar) * 512 + ak4 + 4];
        float4 w0 = *(const float4*)&lnw[ak4];
        float4 w1 = *(const float4*)&lnw[ak4 + 4];
        float4 b0 = *(const float4*)&lnb[ak4];
        float4 b1 = *(const float4*)&lnb[ak4 + 4];
        la0.x = (r0.x - st.x) * st.y * w0.x + b0.x;
        la0.y = (r0.y - st.x) * st.y * w0.y + b0.y;
        la0.z = (r0.z - st.x) * st.y * w0.z + b0.z;
        la0.w = (r0.w - st.x) * st.y * w0.w + b0.w;
        la1.x = (r1.x - st.x) * st.y * w1.x + b1.x;
        la1.y = (r1.y - st.x) * st.y * w1.y + b1.y;
        la1.z = (r1.z - st.x) * st.y * w1.z + b1.z;
        la1.w = (r1.w - st.x) * st.y * w1.w + b1.w;
    }
    lb0 = *(const float4*)&B[(size_t)bk * 512 + n0 + bn];
    lb1 = *(const float4*)&B[(size_t)bk * 512 + n0 + bn + 4];
    {
        As[0][ak4 + 0][ar] = la0.x; As[0][ak4 + 1][ar] = la0.y;
        As[0][ak4 + 2][ar] = la0.z; As[0][ak4 + 3][ar] = la0.w;
        As[0][ak4 + 4][ar] = la1.x; As[0][ak4 + 5][ar] = la1.y;
        As[0][ak4 + 6][ar] = la1.z; As[0][ak4 + 7][ar] = la1.w;
        *(float4*)&Bs[0][bk][bn]     = lb0;
        *(float4*)&Bs[0][bk][bn + 4] = lb1;
    }
    __syncthreads();

    for (int kt = 0; kt < 32; ++kt) {
        const int buf = kt & 1;
        if (kt < 31) {
            const int k0 = (kt + 1) * 16;
            float4 r0 = *(const float4*)&A[(m0 + ar) * 512 + k0 + ak4];
            float4 r1 = *(const float4*)&A[(m0 + ar) * 512 + k0 + ak4 + 4];
            float4 w0 = *(const float4*)&lnw[k0 + ak4];
            float4 w1 = *(const float4*)&lnw[k0 + ak4 + 4];
            float4 b0 = *(const float4*)&lnb[k0 + ak4];
            float4 b1 = *(const float4*)&lnb[k0 + ak4 + 4];
            la0.x = (r0.x - st.x) * st.y * w0.x + b0.x;
            la0.y = (r0.y - st.x) * st.y * w0.y + b0.y;
            la0.z = (r0.z - st.x) * st.y * w0.z + b0.z;
            la0.w = (r0.w - st.x) * st.y * w0.w + b0.w;
            la1.x = (r1.x - st.x) * st.y * w1.x + b1.x;
            la1.y = (r1.y - st.x) * st.y * w1.y + b1.y;
            la1.z = (r1.z - st.x) * st.y * w1.z + b1.z;
            la1.w = (r1.w - st.x) * st.y * w1.w + b1.w;
            lb0 = *(const float4*)&B[(size_t)(k0 + bk) * 512 + n0 + bn];
            lb1 = *(const float4*)&B[(size_t)(k0 + bk) * 512 + n0 + bn + 4];
        }
        #pragma unroll
        for (int kk = 0; kk < 16; ++kk) {
            float4 a0 = *(const float4*)&As[buf][kk][ty * 8];
            float4 a1 = *(const float4*)&As[buf][kk][ty * 8 + 4];
            u64 b0 = *(const u64*)&Bs[buf][kk][2 * tx];
            u64 b1 = *(const u64*)&Bs[buf][kk][2 * tx + 32];
            u64 b2 = *(const u64*)&Bs[buf][kk][2 * tx + 64];
            u64 b3 = *(const u64*)&Bs[buf][kk][2 * tx + 96];
            float av[8] = {a0.x, a0.y, a0.z, a0.w, a1.x, a1.y, a1.z, a1.w};
            #pragma unroll
            for (int i = 0; i < 8; ++i) {
                u64 ai = pk2(av[i], av[i]);
                acc[i][0] = fma2(ai, b0, acc[i][0]);
                acc[i][1] = fma2(ai, b1, acc[i][1]);
                acc[i][2] = fma2(ai, b2, acc[i][2]);
                acc[i][3] = fma2(ai, b3, acc[i][3]);
            }
        }
        if (kt < 31) {
            const int nb = 1 - buf;
            As[nb][ak4 + 0][ar] = la0.x; As[nb][ak4 + 1][ar] = la0.y;
            As[nb][ak4 + 2][ar] = la0.z; As[nb][ak4 + 3][ar] = la0.w;
            As[nb][ak4 + 4][ar] = la1.x; As[nb][ak4 + 5][ar] = la1.y;
            As[nb][ak4 + 6][ar] = la1.z; As[nb][ak4 + 7][ar] = la1.w;
            *(float4*)&Bs[nb][bk][bn]     = lb0;
            *(float4*)&Bs[nb][bk][bn + 4] = lb1;
        }
        __syncthreads();
    }

    #pragma unroll
    for (int j = 0; j < 4; ++j) {
        const int col = n0 + 2 * tx + 32 * j;
        float2 bb = *(const float2*)&bias[col];
        #pragma unroll
        for (int i = 0; i < 8; ++i) {
            float o0, o1; upk2(acc[i][j], o0, o1);
            *(float2*)&C[(m0 + ty * 8 + i) * 512 + col] =
                make_float2(o0 + bb.x, o1 + bb.y);
        }
    }
}

__global__ __launch_bounds__(256) void sgemm_big3(
    const float* __restrict__ Aq, const float2* __restrict__ Sq, const float* __restrict__ W1q, const float* __restrict__ B1q, const float* __restrict__ Wq, const float* __restrict__ Bq, float* __restrict__ Cq,
    const float* __restrict__ Ak, const float2* __restrict__ Sk, const float* __restrict__ W1k, const float* __restrict__ B1k, const float* __restrict__ Wk, const float* __restrict__ Bk, float* __restrict__ Ck,
    const float* __restrict__ Av, const float2* __restrict__ Sv, const float* __restrict__ W1v, const float* __restrict__ B1v, const float* __restrict__ Wv, const float* __restrict__ Bv, float* __restrict__ Cv)
{
    const int bx = blockIdx.x;
    const int n0 = blockIdx.y * 128;
    if (bx < 8)
        sgemm_big_body_ln(Aq, Sq, W1q, B1q, Wq, Bq, Cq, (size_t)bx * 128, n0);
    else if (bx < 72)
        sgemm_big_body_ln(Ak, Sk, W1k, B1k, Wk, Bk, Ck, (size_t)(bx - 8) * 128, n0);
    else
        sgemm_big_body_ln(Av, Sv, W1v, B1v, Wv, Bv, Cv, (size_t)(bx - 72) * 128, n0);
}

// ---------------------------------------------------------------------------
// Tail GEMM, 2-way split-K with atomic accumulation into pre-zeroed C.
// 32x128 tile, 256 threads, 2x8 thread tile, optional fused LN.
// grid (M/32, 4, 2); blockIdx.z = K half. Split 0 adds bias.
// ---------------------------------------------------------------------------
__global__ __launch_bounds__(256) void sgemm_tail(
    const float* __restrict__ A, const float* __restrict__ B,
    const float* __restrict__ bias, float* __restrict__ C,
    const float2* __restrict__ stats, const float* __restrict__ lnw,
    const float* __restrict__ lnb, int do_ln)
{
    __shared__ float As[2][16][36];
    __shared__ float Bs[2][16][132];

    const int tid = threadIdx.x;
    const int ty = tid >> 4;
    const int tx = tid & 15;
    const size_t m0 = (size_t)blockIdx.x * 32;
    const int n0 = blockIdx.y * 128;
    const int kbase = blockIdx.z * 256;

    const int ar  = tid >> 2;
    const int ak4 = (tid & 3) * 4;
    const int bk  = tid >> 4;
    const int bn  = (tid & 15) * 8;
    const bool aload = tid < 128;

    float2 st = make_float2(0.f, 1.f);
    if (do_ln && aload) st = stats[m0 + ar];

    u64 acc[2][4];
    #pragma unroll
    for (int i = 0; i < 2; ++i)
        #pragma unroll
        for (int j = 0; j < 4; ++j) acc[i][j] = 0ull;

    float4 la = make_float4(0, 0, 0, 0);
    float4 lb0, lb1;
    if (aload) {
        float4 r = *(const float4*)&A[(m0 + ar) * 512 + kbase + ak4];
        if (do_ln) {
            float4 w = *(const float4*)&lnw[kbase + ak4];
            float4 b = *(const float4*)&lnb[kbase + ak4];
            la.x = (r.x - st.x) * st.y * w.x + b.x;
            la.y = (r.y - st.x) * st.y * w.y + b.y;
            la.z = (r.z - st.x) * st.y * w.z + b.z;
            la.w = (r.w - st.x) * st.y * w.w + b.w;
        } else la = r;
    }
    lb0 = *(const float4*)&B[(size_t)(kbase + bk) * 512 + n0 + bn];
    lb1 = *(const float4*)&B[(size_t)(kbase + bk) * 512 + n0 + bn + 4];
    if (aload) {
        As[0][ak4 + 0][ar] = la.x; As[0][ak4 + 1][ar] = la.y;
        As[0][ak4 + 2][ar] = la.z; As[0][ak4 + 3][ar] = la.w;
    }
    *(float4*)&Bs[0][bk][bn]     = lb0;
    *(float4*)&Bs[0][bk][bn + 4] = lb1;
    __syncthreads();

    for (int kt = 0; kt < 16; ++kt) {
        const int buf = kt & 1;
        if (kt < 15) {
            const int k0 = kbase + (kt + 1) * 16;
            if (aload) {
                float4 r = *(const float4*)&A[(m0 + ar) * 512 + k0 + ak4];
                if (do_ln) {
                    float4 w = *(const float4*)&lnw[k0 + ak4];
                    float4 b = *(const float4*)&lnb[k0 + ak4];
                    la.x = (r.x - st.x) * st.y * w.x + b.x;
                    la.y = (r.y - st.x) * st.y * w.y + b.y;
                    la.z = (r.z - st.x) * st.y * w.z + b.z;
                    la.w = (r.w - st.x) * st.y * w.w + b.w;
                } else la = r;
            }
            lb0 = *(const float4*)&B[(size_t)(k0 + bk) * 512 + n0 + bn];
            lb1 = *(const float4*)&B[(size_t)(k0 + bk) * 512 + n0 + bn + 4];
        }
        #pragma unroll
        for (int kk = 0; kk < 16; ++kk) {
            float2 a = *(const float2*)&As[buf][kk][ty * 2];
            u64 b0 = *(const u64*)&Bs[buf][kk][2 * tx];
            u64 b1 = *(const u64*)&Bs[buf][kk][2 * tx + 32];
            u64 b2 = *(const u64*)&Bs[buf][kk][2 * tx + 64];
            u64 b3 = *(const u64*)&Bs[buf][kk][2 * tx + 96];
            u64 a0 = pk2(a.x, a.x), a1 = pk2(a.y, a.y);
            acc[0][0] = fma2(a0, b0, acc[0][0]);
            acc[0][1] = fma2(a0, b1, acc[0][1]);
            acc[0][2] = fma2(a0, b2, acc[0][2]);
            acc[0][3] = fma2(a0, b3, acc[0][3]);
            acc[1][0] = fma2(a1, b0, acc[1][0]);
            acc[1][1] = fma2(a1, b1, acc[1][1]);
            acc[1][2] = fma2(a1, b2, acc[1][2]);
            acc[1][3] = fma2(a1, b3, acc[1][3]);
        }
        if (kt < 15) {
            const int nb = 1 - buf;
            if (aload) {
                As[nb][ak4 + 0][ar] = la.x; As[nb][ak4 + 1][ar] = la.y;
                As[nb][ak4 + 2][ar] = la.z; As[nb][ak4 + 3][ar] = la.w;
            }
            *(float4*)&Bs[nb][bk][bn]     = lb0;
            *(float4*)&Bs[nb][bk][bn + 4] = lb1;
        }
        __syncthreads();
    }

    const bool addb = (blockIdx.z == 0);
    #pragma unroll
    for (int j = 0; j < 4; ++j) {
        const int col = n0 + 2 * tx + 32 * j;
        float2 bb = addb ? *(const float2*)&bias[col] : make_float2(0.f, 0.f);
        #pragma unroll
        for (int i = 0; i < 2; ++i) {
            float o0, o1; upk2(acc[i][j], o0, o1);
            float* cp = &C[(m0 + ty * 2 + i) * 512 + col];
            atomicAdd(cp,     o0 + bb.x);
            atomicAdd(cp + 1, o1 + bb.y);
        }
    }
}

// ---------------------------------------------------------------------------
// Fused ColBERT attention — EXACT R7 structure (best measured, ~283us)
// plus the single validated improvement: per-lane partial softmax
// denominator (final shfl-reduce once after the loop), and Q pre-scaled.
// Block 256 thr / 8 warps, grid (16, 8). 64-token tile, 8 rows/warp,
// 64 chunks of 32 contexts, cp.async double-buffered staging, swizzled K,
// smem p-transpose AV with pk2 duplication (ALU pipe, crossbar-light).
// smem floats: qs[4096] | ks 2x[8192] | vs 2x[2048] | pd[2048] = 26624
// ---------------------------------------------------------------------------
#define ATT_SMEM (26624 * 4)

__global__ __launch_bounds__(256) void attn_kernel(
    const float* __restrict__ q, const float* __restrict__ k,
    const float* __restrict__ v, float* __restrict__ outp)
{
    extern __shared__ float sm[];
    float* qs  = sm;             // [64][64], pre-scaled by 0.125
    float* ksb = sm + 4096;      // 2 x [u][cc][64] swizzled
    float* vsb = sm + 20480;     // 2 x [cc][64]
    float* pd  = sm + 24576;     // [warp][cc][8]

    const int tid  = threadIdx.x;
    const int w    = tid >> 5;
    const int lane = tid & 31;
    const int h    = blockIdx.y;
    const int bt0  = blockIdx.x * 64;
    const int r0   = w * 8;
    const int sw   = (lane & 7) << 2;
    const uint32_t smb = smem_u32(sm);

    const int scc = tid >> 3, srr = tid & 7;
    const float* kg = k + ((size_t)scc * 4) * 512 + h * 64 + srr * 4;
    const uint32_t koff0 = (uint32_t)(scc * 64 + ((srr * 4) ^ ((scc & 7) << 2)));
    const float* vg = v + (size_t)(tid >> 4) * 512 + h * 64 + (tid & 15) * 4;
    const uint32_t voff0 = (uint32_t)((tid >> 4) * 64 + (tid & 15) * 4);

    // Q staging with 1/8 scale folded in: 1024 float4
    #pragma unroll
    for (int j = 0; j < 4; ++j) {
        int i = tid + 256 * j;
        int dd = i & 15, r = i >> 4;
        float4 t = *(const float4*)&q[(size_t)(bt0 + r) * 512 + h * 64 + dd * 4];
        *(float4*)&qs[r * 64 + dd * 4] =
            make_float4(t.x * 0.125f, t.y * 0.125f, t.z * 0.125f, t.w * 0.125f);
    }

    auto stage = [&](int b, int c) {
        const float* kp = kg + (size_t)c * 65536;
        const uint32_t kd = smb + (4096 + b * 8192 + koff0) * 4;
        #pragma unroll
        for (int j = 0; j < 8; ++j)
            CP_ASYNC16(kd + (uint32_t)(((j & 1) * 32 + (j >> 1) * 2048) * 4),
                       kp + (j >> 1) * 512 + (j & 1) * 32);
        const float* vp = vg + (size_t)c * 16384;
        const uint32_t vd = smb + (20480 + b * 2048 + voff0) * 4;
        CP_ASYNC16(vd, vp);
        CP_ASYNC16(vd + 1024 * 4, vp + 8192);
    };

    stage(0, 0); CP_COMMIT();

    float m[8], lp[8];          // lp = per-lane partial denominator
    u64 o2[8];
    #pragma unroll
    for (int r = 0; r < 8; ++r) { m[r] = -1e30f; lp[r] = 0.f; o2[r] = 0ull; }

    float* pw = pd + w * 256;

    for (int c = 0; c < 64; ++c) {
        const int buf = c & 1;
        if (c < 63) { stage(buf ^ 1, c + 1); CP_COMMIT(); CP_WAIT(1); }
        else        { CP_WAIT(0); }
        __syncthreads();

        const float* ks = ksb + buf * 8192;
        const float* vs = vsb + buf * 2048;
        const float* kb = ks + lane * 64;

        // ---- scores: acc[r][u], 8 rows x 4 u per warp
        u64 acc[8][4];
        #pragma unroll
        for (int r = 0; r < 8; ++r)
            #pragma unroll
            for (int u = 0; u < 4; ++u) acc[r][u] = 0ull;

        #pragma unroll
        for (int d4 = 0; d4 < 64; d4 += 4) {
            const int off = d4 ^ sw;
            ulonglong2 k0 = *(const ulonglong2*)&kb[off];
            ulonglong2 k1 = *(const ulonglong2*)&kb[off + 2048];
            ulonglong2 k2 = *(const ulonglong2*)&kb[off + 4096];
            ulonglong2 k3 = *(const ulonglong2*)&kb[off + 6144];
            #pragma unroll
            for (int r = 0; r < 8; ++r) {
                ulonglong2 qq = *(const ulonglong2*)&qs[(r0 + r) * 64 + d4];
                acc[r][0] = fma2(qq.x, k0.x, acc[r][0]);
                acc[r][0] = fma2(qq.y, k0.y, acc[r][0]);
                acc[r][1] = fma2(qq.x, k1.x, acc[r][1]);
                acc[r][1] = fma2(qq.y, k1.y, acc[r][1]);
                acc[r][2] = fma2(qq.x, k2.x, acc[r][2]);
                acc[r][2] = fma2(qq.y, k2.y, acc[r][2]);
                acc[r][3] = fma2(qq.x, k3.x, acc[r][3]);
                acc[r][3] = fma2(qq.y, k3.y, acc[r][3]);
            }
        }

        // ---- MaxSim + online softmax (max shfl only; l per-lane)
        float pv[8];
        #pragma unroll
        for (int r = 0; r < 8; ++r) {
            float x0, x1, s;
            upk2(acc[r][0], x0, x1); s = x0 + x1;
            upk2(acc[r][1], x0, x1); s = fmaxf(s, x0 + x1);
            upk2(acc[r][2], x0, x1); s = fmaxf(s, x0 + x1);
            upk2(acc[r][3], x0, x1); s = fmaxf(s, x0 + x1);
            float cm = s;
            #pragma unroll
            for (int o = 16; o; o >>= 1)
                cm = fmaxf(cm, __shfl_xor_sync(0xffffffffu, cm, o));
            float mn   = fmaxf(m[r], cm);
            float corr = __expf(m[r] - mn);
            pv[r] = __expf(s - mn);
            lp[r] = lp[r] * corr + pv[r];
            m[r] = mn;
            o2[r] = mul2(o2[r], pk2(corr, corr));
        }

        // transpose p through smem: pd[w][cc][r]
        *(float4*)&pw[lane * 8]     = make_float4(pv[0], pv[1], pv[2], pv[3]);
        *(float4*)&pw[lane * 8 + 4] = make_float4(pv[4], pv[5], pv[6], pv[7]);
        __syncwarp();

        // ---- AV: o[r][2lane..] += p[r][j] * v[j][2lane..]
        #pragma unroll 4
        for (int j = 0; j < 32; ++j) {
            u64 vj = *(const u64*)&vs[j * 64 + 2 * lane];
            float4 pa = *(const float4*)&pw[j * 8];
            float4 pb = *(const float4*)&pw[j * 8 + 4];
            o2[0] = fma2(pk2(pa.x, pa.x), vj, o2[0]);
            o2[1] = fma2(pk2(pa.y, pa.y), vj, o2[1]);
            o2[2] = fma2(pk2(pa.z, pa.z), vj, o2[2]);
            o2[3] = fma2(pk2(pa.w, pa.w), vj, o2[3]);
            o2[4] = fma2(pk2(pb.x, pb.x), vj, o2[4]);
            o2[5] = fma2(pk2(pb.y, pb.y), vj, o2[5]);
            o2[6] = fma2(pk2(pb.z, pb.z), vj, o2[6]);
            o2[7] = fma2(pk2(pb.w, pb.w), vj, o2[7]);
        }
        __syncwarp();
        __syncthreads();
    }

    // ---- final l reduce + normalize + write
    #pragma unroll
    for (int r = 0; r < 8; ++r) {
        float ls = lp[r];
        #pragma unroll
        for (int o = 16; o; o >>= 1)
            ls += __shfl_xor_sync(0xffffffffu, ls, o);
        float inv = 1.f / ls;
        float lo, hi; upk2(o2[r], lo, hi);
        *(float2*)&outp[(size_t)(bt0 + r0 + r) * 512 + h * 64 + 2 * lane] =
            make_float2(lo * inv, hi * inv);
    }
}

// ---------------------------------------------------------------------------
extern "C" void kernel_launch(void* const* d_in, const int* in_sizes, int n_in,
                              void* d_out, int out_size)
{
    const float* model_embed = (const float*)d_in[0];
    const float* ctx_key     = (const float*)d_in[1];
    const float* ctx_val     = (const float*)d_in[2];
    const float* ln1w = (const float*)d_in[3];
    const float* ln1b = (const float*)d_in[4];
    const float* ln2w = (const float*)d_in[5];
    const float* ln2b = (const float*)d_in[6];
    const float* ln3w = (const float*)d_in[7];
    const float* ln3b = (const float*)d_in[8];
    const float* ln4w = (const float*)d_in[9];
    const float* ln4b = (const float*)d_in[10];
    const float* wq = (const float*)d_in[11];
    const float* bq = (const float*)d_in[12];
    const float* wk = (const float*)d_in[13];
    const float* bk = (const float*)d_in[14];
    const float* wv = (const float*)d_in[15];
    const float* bv = (const float*)d_in[16];
    const float* wo = (const float*)d_in[17];
    const float* bo = (const float*)d_in[18];
    const float* wp = (const float*)d_in[19];
    const float* bp = (const float*)d_in[20];

    float2 *stats, *stats4;
    float *q, *k, *v, *att, *o;
    cudaGetSymbolAddress((void**)&stats,  g_stats);
    cudaGetSymbolAddress((void**)&stats4, g_stats4);
    cudaGetSymbolAddress((void**)&q,    g_q);
    cudaGetSymbolAddress((void**)&k,    g_k);
    cudaGetSymbolAddress((void**)&v,    g_v);
    cudaGetSymbolAddress((void**)&att,  g_att);
    cudaGetSymbolAddress((void**)&o,    g_o);

    static int attr_set = 0;
    if (!attr_set) {
        cudaFuncSetAttribute(attn_kernel,
                             cudaFuncAttributeMaxDynamicSharedMemorySize, ATT_SMEM);
        attr_set = 1;
    }

    // zero atomic-accumulation targets for split-K
    zero2<<<1024, 256>>>(o, (float*)d_out);

    // LN stats + fused LN+GEMM projections
    ln_stats3<<<1408, 256>>>(model_embed, ctx_key, ctx_val, stats);
    sgemm_big3<<<dim3(88, 4), 256>>>(
        model_embed, stats,        ln1w, ln1b, wq, bq, q,
        ctx_key,     stats + 1024, ln2w, ln2b, wk, bk, k,
        ctx_val,     stats + 9216, ln3w, ln3b, wv, bv, v);

    // fused MaxSim attention (R7 structure + per-lane l)
    attn_kernel<<<dim3(16, 8), 256, ATT_SMEM>>>(q, k, v, att);

    // output proj (split-K 2x), LN4 stats, final proj (split-K 2x, fused LN)
    sgemm_tail<<<dim3(32, 4, 2), 256>>>(att, wo, bo, o, nullptr, nullptr, nullptr, 0);
    ln_stats1<<<128, 256>>>(o, stats4);
    sgemm_tail<<<dim3(32, 4, 2), 256>>>(o, wp, bp, (float*)d_out, stats4, ln4w, ln4b, 1);
}

// round 14
// speedup vs baseline: 1.0887x; 1.0040x over previous
#include <cuda_runtime.h>
#include <cstdint>
#include <math.h>

// Shapes fixed: B=4, T=256, C=2048, U=4, D=512, P=512, H=8, dk=64

__device__ float2 g_stats[11264];   // mu/rstd for q(1024)|k(8192)|v(2048) rows
__device__ float2 g_stats4[1024];   // mu/rstd for LN4
__device__ float g_q  [1024 * 512];
__device__ float g_k  [8192 * 512];
__device__ float g_v  [2048 * 512];
__device__ float g_att[1024 * 512];
__device__ float g_o  [1024 * 512];

typedef unsigned long long u64;

__device__ __forceinline__ u64 pk2(float lo, float hi) {
    u64 r; asm("mov.b64 %0, {%1, %2};" : "=l"(r) : "f"(lo), "f"(hi)); return r;
}
__device__ __forceinline__ void upk2(u64 v, float& lo, float& hi) {
    asm("mov.b64 {%0, %1}, %2;" : "=f"(lo), "=f"(hi) : "l"(v));
}
__device__ __forceinline__ u64 fma2(u64 a, u64 b, u64 c) {
    u64 d; asm("fma.rn.f32x2 %0, %1, %2, %3;" : "=l"(d) : "l"(a), "l"(b), "l"(c)); return d;
}
__device__ __forceinline__ u64 mul2(u64 a, u64 b) {
    u64 d; asm("mul.rn.f32x2 %0, %1, %2;" : "=l"(d) : "l"(a), "l"(b)); return d;
}
__device__ __forceinline__ uint32_t smem_u32(const void* p) {
    uint32_t a;
    asm("{ .reg .u64 t; cvta.to.shared.u64 t, %1; cvt.u32.u64 %0, t; }" : "=r"(a) : "l"(p));
    return a;
}
#define CP_ASYNC16(dst, src) \
    asm volatile("cp.async.cg.shared.global [%0], [%1], 16;" :: "r"(dst), "l"(src) : "memory")
#define CP_COMMIT() asm volatile("cp.async.commit_group;" ::: "memory")
#define CP_WAIT(n)  asm volatile("cp.async.wait_group %0;" :: "n"(n) : "memory")

// ---------------------------------------------------------------------------
// zero both atomic-accumulation targets (g_o, d_out): 2 x 524288 floats.
// ---------------------------------------------------------------------------
__global__ __launch_bounds__(256) void zero2(float* __restrict__ a, float* __restrict__ b)
{
    int i = blockIdx.x * 256 + threadIdx.x;
    if (i < 131072) *(float4*)&a[i * 4] = make_float4(0.f, 0.f, 0.f, 0.f);
    else { i -= 131072; *(float4*)&b[i * 4] = make_float4(0.f, 0.f, 0.f, 0.f); }
}

// ---------------------------------------------------------------------------
// LN stats: one warp per row, D=512. Writes (mu, rstd).
// ---------------------------------------------------------------------------
__device__ __forceinline__ void ln_stat_row(
    const float* __restrict__ xr, float2* __restrict__ out, int lane)
{
    float s = 0.f, ss = 0.f;
    #pragma unroll
    for (int j = 0; j < 4; ++j) {
        float4 x = *(const float4*)&xr[j * 128 + lane * 4];
        s  += x.x + x.y + x.z + x.w;
        ss += x.x * x.x + x.y * x.y + x.z * x.z + x.w * x.w;
    }
    #pragma unroll
    for (int o = 16; o; o >>= 1) {
        s  += __shfl_xor_sync(0xffffffffu, s, o);
        ss += __shfl_xor_sync(0xffffffffu, ss, o);
    }
    if (lane == 0) {
        float mu = s * (1.f / 512.f);
        float rstd = rsqrtf(ss * (1.f / 512.f) - mu * mu + 1e-5f);
        *out = make_float2(mu, rstd);
    }
}

__global__ __launch_bounds__(256) void ln_stats3(
    const float* __restrict__ x0, const float* __restrict__ x1,
    const float* __restrict__ x2, float2* __restrict__ st)
{
    const int lane = threadIdx.x & 31;
    const int wr = threadIdx.x >> 5;
    const int bx = blockIdx.x;
    const float* x; size_t row; float2* o;
    if (bx < 128)       { x = x0; row = (size_t)bx * 8 + wr; o = st; }
    else if (bx < 1152) { x = x1; row = (size_t)(bx - 128) * 8 + wr; o = st + 1024; }
    else                { x = x2; row = (size_t)(bx - 1152) * 8 + wr; o = st + 9216; }
    ln_stat_row(x + row * 512, o + row, lane);
}

__global__ __launch_bounds__(256) void ln_stats1(
    const float* __restrict__ x, float2* __restrict__ st)
{
    const int lane = threadIdx.x & 31;
    const size_t row = (size_t)blockIdx.x * 8 + (threadIdx.x >> 5);
    ln_stat_row(x + row * 512, st + row, lane);
}

// ---------------------------------------------------------------------------
// sgemm_big with fused LN on A-load: 128x128 tile, BK=16, 256 thr, 8x8 tile.
// ---------------------------------------------------------------------------
__device__ __forceinline__ void sgemm_big_body_ln(
    const float* __restrict__ A, const float2* __restrict__ stats,
    const float* __restrict__ lnw, const float* __restrict__ lnb,
    const float* __restrict__ B, const float* __restrict__ bias,
    float* __restrict__ C, size_t m0, int n0)
{
    __shared__ float As[2][16][132];
    __shared__ float Bs[2][16][132];

    const int tid = threadIdx.x;
    const int ty = tid >> 4, tx = tid & 15;
    const int ar = tid >> 1, ak4 = (tid & 1) * 8;
    const int bk = tid >> 4, bn = (tid & 15) * 8;

    const float2 st = stats[m0 + ar];

    u64 acc[8][4];
    #pragma unroll
    for (int i = 0; i < 8; ++i)
        #pragma unroll
        for (int j = 0; j < 4; ++j) acc[i][j] = 0ull;

    float4 la0, la1, lb0, lb1;
    {
        float4 r0 = *(const float4*)&A[(m0 + ar) * 512 + ak4];
        float4 r1 = *(const float4*)&A[(m0 + ar) * 512 + ak4 + 4];
        float4 w0 = *(const float4*)&lnw[ak4];
        float4 w1 = *(const float4*)&lnw[ak4 + 4];
        float4 b0 = *(const float4*)&lnb[ak4];
        float4 b1 = *(const float4*)&lnb[ak4 + 4];
        la0.x = (r0.x - st.x) * st.y * w0.x + b0.x;
        la0.y = (r0.y - st.x) * st.y * w0.y + b0.y;
        la0.z = (r0.z - st.x) * st.y * w0.z + b0.z;
        la0.w = (r0.w - st.x) * st.y * w0.w + b0.w;
        la1.x = (r1.x - st.x) * st.y * w1.x + b1.x;
        la1.y = (r1.y - st.x) * st.y * w1.y + b1.y;
        la1.z = (r1.z - st.x) * st.y * w1.z + b1.z;
        la1.w = (r1.w - st.x) * st.y * w1.w + b1.w;
    }
    lb0 = *(const float4*)&B[(size_t)bk * 512 + n0 + bn];
    lb1 = *(const float4*)&B[(size_t)bk * 512 + n0 + bn + 4];
    {
        As[0][ak4 + 0][ar] = la0.x; As[0][ak4 + 1][ar] = la0.y;
        As[0][ak4 + 2][ar] = la0.z; As[0][ak4 + 3][ar] = la0.w;
        As[0][ak4 + 4][ar] = la1.x; As[0][ak4 + 5][ar] = la1.y;
        As[0][ak4 + 6][ar] = la1.z; As[0][ak4 + 7][ar] = la1.w;
        *(float4*)&Bs[0][bk][bn]     = lb0;
        *(float4*)&Bs[0][bk][bn + 4] = lb1;
    }
    __syncthreads();

    for (int kt = 0; kt < 32; ++kt) {
        const int buf = kt & 1;
        if (kt < 31) {
            const int k0 = (kt + 1) * 16;
            float4 r0 = *(const float4*)&A[(m0 + ar) * 512 + k0 + ak4];
            float4 r1 = *(const float4*)&A[(m0 + ar) * 512 + k0 + ak4 + 4];
            float4 w0 = *(const float4*)&lnw[k0 + ak4];
            float4 w1 = *(const float4*)&lnw[k0 + ak4 + 4];
            float4 b0 = *(const float4*)&lnb[k0 + ak4];
            float4 b1 = *(const float4*)&lnb[k0 + ak4 + 4];
            la0.x = (r0.x - st.x) * st.y * w0.x + b0.x;
            la0.y = (r0.y - st.x) * st.y * w0.y + b0.y;
            la0.z = (r0.z - st.x) * st.y * w0.z + b0.z;
            la0.w = (r0.w - st.x) * st.y * w0.w + b0.w;
            la1.x = (r1.x - st.x) * st.y * w1.x + b1.x;
            la1.y = (r1.y - st.x) * st.y * w1.y + b1.y;
            la1.z = (r1.z - st.x) * st.y * w1.z + b1.z;
            la1.w = (r1.w - st.x) * st.y * w1.w + b1.w;
            lb0 = *(const float4*)&B[(size_t)(k0 + bk) * 512 + n0 + bn];
            lb1 = *(const float4*)&B[(size_t)(k0 + bk) * 512 + n0 + bn + 4];
        }
        #pragma unroll
        for (int kk = 0; kk < 16; ++kk) {
            float4 a0 = *(const float4*)&As[buf][kk][ty * 8];
            float4 a1 = *(const float4*)&As[buf][kk][ty * 8 + 4];
            u64 b0 = *(const u64*)&Bs[buf][kk][2 * tx];
            u64 b1 = *(const u64*)&Bs[buf][kk][2 * tx + 32];
            u64 b2 = *(const u64*)&Bs[buf][kk][2 * tx + 64];
            u64 b3 = *(const u64*)&Bs[buf][kk][2 * tx + 96];
            float av[8] = {a0.x, a0.y, a0.z, a0.w, a1.x, a1.y, a1.z, a1.w};
            #pragma unroll
            for (int i = 0; i < 8; ++i) {
                u64 ai = pk2(av[i], av[i]);
                acc[i][0] = fma2(ai, b0, acc[i][0]);
                acc[i][1] = fma2(ai, b1, acc[i][1]);
                acc[i][2] = fma2(ai, b2, acc[i][2]);
                acc[i][3] = fma2(ai, b3, acc[i][3]);
            }
        }
        if (kt < 31) {
            const int nb = 1 - buf;
            As[nb][ak4 + 0][ar] = la0.x; As[nb][ak4 + 1][ar] = la0.y;
            As[nb][ak4 + 2][ar] = la0.z; As[nb][ak4 + 3][ar] = la0.w;
            As[nb][ak4 + 4][ar] = la1.x; As[nb][ak4 + 5][ar] = la1.y;
            As[nb][ak4 + 6][ar] = la1.z; As[nb][ak4 + 7][ar] = la1.w;
            *(float4*)&Bs[nb][bk][bn]     = lb0;
            *(float4*)&Bs[nb][bk][bn + 4] = lb1;
        }
        __syncthreads();
    }

    #pragma unroll
    for (int j = 0; j < 4; ++j) {
        const int col = n0 + 2 * tx + 32 * j;
        float2 bb = *(const float2*)&bias[col];
        #pragma unroll
        for (int i = 0; i < 8; ++i) {
            float o0, o1; upk2(acc[i][j], o0, o1);
            *(float2*)&C[(m0 + ty * 8 + i) * 512 + col] =
                make_float2(o0 + bb.x, o1 + bb.y);
        }
    }
}

__global__ __launch_bounds__(256) void sgemm_big3(
    const float* __restrict__ Aq, const float2* __restrict__ Sq, const float* __restrict__ W1q, const float* __restrict__ B1q, const float* __restrict__ Wq, const float* __restrict__ Bq, float* __restrict__ Cq,
    const float* __restrict__ Ak, const float2* __restrict__ Sk, const float* __restrict__ W1k, const float* __restrict__ B1k, const float* __restrict__ Wk, const float* __restrict__ Bk, float* __restrict__ Ck,
    const float* __restrict__ Av, const float2* __restrict__ Sv, const float* __restrict__ W1v, const float* __restrict__ B1v, const float* __restrict__ Wv, const float* __restrict__ Bv, float* __restrict__ Cv)
{
    const int bx = blockIdx.x;
    const int n0 = blockIdx.y * 128;
    if (bx < 8)
        sgemm_big_body_ln(Aq, Sq, W1q, B1q, Wq, Bq, Cq, (size_t)bx * 128, n0);
    else if (bx < 72)
        sgemm_big_body_ln(Ak, Sk, W1k, B1k, Wk, Bk, Ck, (size_t)(bx - 8) * 128, n0);
    else
        sgemm_big_body_ln(Av, Sv, W1v, B1v, Wv, Bv, Cv, (size_t)(bx - 72) * 128, n0);
}

// ---------------------------------------------------------------------------
// Tail GEMM, 2-way split-K with atomic accumulation into pre-zeroed C.
// 32x128 tile, 256 threads, 2x8 thread tile, optional fused LN.
// grid (M/32, 4, 2); blockIdx.z = K half. Split 0 adds bias.
// ---------------------------------------------------------------------------
__global__ __launch_bounds__(256) void sgemm_tail(
    const float* __restrict__ A, const float* __restrict__ B,
    const float* __restrict__ bias, float* __restrict__ C,
    const float2* __restrict__ stats, const float* __restrict__ lnw,
    const float* __restrict__ lnb, int do_ln)
{
    __shared__ float As[2][16][36];
    __shared__ float Bs[2][16][132];

    const int tid = threadIdx.x;
    const int ty = tid >> 4;
    const int tx = tid & 15;
    const size_t m0 = (size_t)blockIdx.x * 32;
    const int n0 = blockIdx.y * 128;
    const int kbase = blockIdx.z * 256;

    const int ar  = tid >> 2;
    const int ak4 = (tid & 3) * 4;
    const int bk  = tid >> 4;
    const int bn  = (tid & 15) * 8;
    const bool aload = tid < 128;

    float2 st = make_float2(0.f, 1.f);
    if (do_ln && aload) st = stats[m0 + ar];

    u64 acc[2][4];
    #pragma unroll
    for (int i = 0; i < 2; ++i)
        #pragma unroll
        for (int j = 0; j < 4; ++j) acc[i][j] = 0ull;

    float4 la = make_float4(0, 0, 0, 0);
    float4 lb0, lb1;
    if (aload) {
        float4 r = *(const float4*)&A[(m0 + ar) * 512 + kbase + ak4];
        if (do_ln) {
            float4 w = *(const float4*)&lnw[kbase + ak4];
            float4 b = *(const float4*)&lnb[kbase + ak4];
            la.x = (r.x - st.x) * st.y * w.x + b.x;
            la.y = (r.y - st.x) * st.y * w.y + b.y;
            la.z = (r.z - st.x) * st.y * w.z + b.z;
            la.w = (r.w - st.x) * st.y * w.w + b.w;
        } else la = r;
    }
    lb0 = *(const float4*)&B[(size_t)(kbase + bk) * 512 + n0 + bn];
    lb1 = *(const float4*)&B[(size_t)(kbase + bk) * 512 + n0 + bn + 4];
    if (aload) {
        As[0][ak4 + 0][ar] = la.x; As[0][ak4 + 1][ar] = la.y;
        As[0][ak4 + 2][ar] = la.z; As[0][ak4 + 3][ar] = la.w;
    }
    *(float4*)&Bs[0][bk][bn]     = lb0;
    *(float4*)&Bs[0][bk][bn + 4] = lb1;
    __syncthreads();

    for (int kt = 0; kt < 16; ++kt) {
        const int buf = kt & 1;
        if (kt < 15) {
            const int k0 = kbase + (kt + 1) * 16;
            if (aload) {
                float4 r = *(const float4*)&A[(m0 + ar) * 512 + k0 + ak4];
                if (do_ln) {
                    float4 w = *(const float4*)&lnw[k0 + ak4];
                    float4 b = *(const float4*)&lnb[k0 + ak4];
                    la.x = (r.x - st.x) * st.y * w.x + b.x;
                    la.y = (r.y - st.x) * st.y * w.y + b.y;
                    la.z = (r.z - st.x) * st.y * w.z + b.z;
                    la.w = (r.w - st.x) * st.y * w.w + b.w;
                } else la = r;
            }
            lb0 = *(const float4*)&B[(size_t)(k0 + bk) * 512 + n0 + bn];
            lb1 = *(const float4*)&B[(size_t)(k0 + bk) * 512 + n0 + bn + 4];
        }
        #pragma unroll
        for (int kk = 0; kk < 16; ++kk) {
            float2 a = *(const float2*)&As[buf][kk][ty * 2];
            u64 b0 = *(const u64*)&Bs[buf][kk][2 * tx];
            u64 b1 = *(const u64*)&Bs[buf][kk][2 * tx + 32];
            u64 b2 = *(const u64*)&Bs[buf][kk][2 * tx + 64];
            u64 b3 = *(const u64*)&Bs[buf][kk][2 * tx + 96];
            u64 a0 = pk2(a.x, a.x), a1 = pk2(a.y, a.y);
            acc[0][0] = fma2(a0, b0, acc[0][0]);
            acc[0][1] = fma2(a0, b1, acc[0][1]);
            acc[0][2] = fma2(a0, b2, acc[0][2]);
            acc[0][3] = fma2(a0, b3, acc[0][3]);
            acc[1][0] = fma2(a1, b0, acc[1][0]);
            acc[1][1] = fma2(a1, b1, acc[1][1]);
            acc[1][2] = fma2(a1, b2, acc[1][2]);
            acc[1][3] = fma2(a1, b3, acc[1][3]);
        }
        if (kt < 15) {
            const int nb = 1 - buf;
            if (aload) {
                As[nb][ak4 + 0][ar] = la.x; As[nb][ak4 + 1][ar] = la.y;
                As[nb][ak4 + 2][ar] = la.z; As[nb][ak4 + 3][ar] = la.w;
            }
            *(float4*)&Bs[nb][bk][bn]     = lb0;
            *(float4*)&Bs[nb][bk][bn + 4] = lb1;
        }
        __syncthreads();
    }

    const bool addb = (blockIdx.z == 0);
    #pragma unroll
    for (int j = 0; j < 4; ++j) {
        const int col = n0 + 2 * tx + 32 * j;
        float2 bb = addb ? *(const float2*)&bias[col] : make_float2(0.f, 0.f);
        #pragma unroll
        for (int i = 0; i < 2; ++i) {
            float o0, o1; upk2(acc[i][j], o0, o1);
            float* cp = &C[(m0 + ty * 2 + i) * 512 + col];
            atomicAdd(cp,     o0 + bb.x);
            atomicAdd(cp + 1, o1 + bb.y);
        }
    }
}

// ---------------------------------------------------------------------------
// Fused ColBERT attention — R13 inner code, but TWO chunks per barrier
// period using 4 K/V buffers (184KB smem): barrier count 128 -> 64.
// Block 256 thr / 8 warps, grid (16, 8). 64-token tile, 8 rows/warp.
// smem floats: qs[4096] | ks 4x[8192] | vs 4x[2048] | pd[2048] = 47104
// ---------------------------------------------------------------------------
#define ATT_SMEM (47104 * 4)

__global__ __launch_bounds__(256) void attn_kernel(
    const float* __restrict__ q, const float* __restrict__ k,
    const float* __restrict__ v, float* __restrict__ outp)
{
    extern __shared__ float sm[];
    float* qs  = sm;             // [64][64], pre-scaled by 0.125
    float* ksb = sm + 4096;      // 4 x [u][cc][64] swizzled
    float* vsb = sm + 36864;     // 4 x [cc][64]
    float* pd  = sm + 45056;     // [warp][cc][8]

    const int tid  = threadIdx.x;
    const int w    = tid >> 5;
    const int lane = tid & 31;
    const int h    = blockIdx.y;
    const int bt0  = blockIdx.x * 64;
    const int r0   = w * 8;
    const int sw   = (lane & 7) << 2;
    const uint32_t smb = smem_u32(sm);

    const int scc = tid >> 3, srr = tid & 7;
    const float* kg = k + ((size_t)scc * 4) * 512 + h * 64 + srr * 4;
    const uint32_t koff0 = (uint32_t)(scc * 64 + ((srr * 4) ^ ((scc & 7) << 2)));
    const float* vg = v + (size_t)(tid >> 4) * 512 + h * 64 + (tid & 15) * 4;
    const uint32_t voff0 = (uint32_t)((tid >> 4) * 64 + (tid & 15) * 4);

    // Q staging with 1/8 scale folded in: 1024 float4
    #pragma unroll
    for (int j = 0; j < 4; ++j) {
        int i = tid + 256 * j;
        int dd = i & 15, r = i >> 4;
        float4 t = *(const float4*)&q[(size_t)(bt0 + r) * 512 + h * 64 + dd * 4];
        *(float4*)&qs[r * 64 + dd * 4] =
            make_float4(t.x * 0.125f, t.y * 0.125f, t.z * 0.125f, t.w * 0.125f);
    }

    auto stage = [&](int b, int c) {
        const float* kp = kg + (size_t)c * 65536;
        const uint32_t kd = smb + (4096 + b * 8192 + koff0) * 4;
        #pragma unroll
        for (int j = 0; j < 8; ++j)
            CP_ASYNC16(kd + (uint32_t)(((j & 1) * 32 + (j >> 1) * 2048) * 4),
                       kp + (j >> 1) * 512 + (j & 1) * 32);
        const float* vp = vg + (size_t)c * 16384;
        const uint32_t vd = smb + (36864 + b * 2048 + voff0) * 4;
        CP_ASYNC16(vd, vp);
        CP_ASYNC16(vd + 1024 * 4, vp + 8192);
    };

    float m[8], lp[8];          // lp = per-lane partial denominator
    u64 o2[8];
    #pragma unroll
    for (int r = 0; r < 8; ++r) { m[r] = -1e30f; lp[r] = 0.f; o2[r] = 0ull; }

    float* pw = pd + w * 256;

    // compute one 32-context chunk from buffer `buf`
    auto compute = [&](int buf) {
        const float* ks = ksb + buf * 8192;
        const float* vs = vsb + buf * 2048;
        const float* kb = ks + lane * 64;

        u64 acc[8][4];
        #pragma unroll
        for (int r = 0; r < 8; ++r)
            #pragma unroll
            for (int u = 0; u < 4; ++u) acc[r][u] = 0ull;

        #pragma unroll
        for (int d4 = 0; d4 < 64; d4 += 4) {
            const int off = d4 ^ sw;
            ulonglong2 k0 = *(const ulonglong2*)&kb[off];
            ulonglong2 k1 = *(const ulonglong2*)&kb[off + 2048];
            ulonglong2 k2 = *(const ulonglong2*)&kb[off + 4096];
            ulonglong2 k3 = *(const ulonglong2*)&kb[off + 6144];
            #pragma unroll
            for (int r = 0; r < 8; ++r) {
                ulonglong2 qq = *(const ulonglong2*)&qs[(r0 + r) * 64 + d4];
                acc[r][0] = fma2(qq.x, k0.x, acc[r][0]);
                acc[r][0] = fma2(qq.y, k0.y, acc[r][0]);
                acc[r][1] = fma2(qq.x, k1.x, acc[r][1]);
                acc[r][1] = fma2(qq.y, k1.y, acc[r][1]);
                acc[r][2] = fma2(qq.x, k2.x, acc[r][2]);
                acc[r][2] = fma2(qq.y, k2.y, acc[r][2]);
                acc[r][3] = fma2(qq.x, k3.x, acc[r][3]);
                acc[r][3] = fma2(qq.y, k3.y, acc[r][3]);
            }
        }

        float pv[8];
        #pragma unroll
        for (int r = 0; r < 8; ++r) {
            float x0, x1, s;
            upk2(acc[r][0], x0, x1); s = x0 + x1;
            upk2(acc[r][1], x0, x1); s = fmaxf(s, x0 + x1);
            upk2(acc[r][2], x0, x1); s = fmaxf(s, x0 + x1);
            upk2(acc[r][3], x0, x1); s = fmaxf(s, x0 + x1);
            float cm = s;
            #pragma unroll
            for (int o = 16; o; o >>= 1)
                cm = fmaxf(cm, __shfl_xor_sync(0xffffffffu, cm, o));
            float mn   = fmaxf(m[r], cm);
            float corr = __expf(m[r] - mn);
            pv[r] = __expf(s - mn);
            lp[r] = lp[r] * corr + pv[r];
            m[r] = mn;
            o2[r] = mul2(o2[r], pk2(corr, corr));
        }

        *(float4*)&pw[lane * 8]     = make_float4(pv[0], pv[1], pv[2], pv[3]);
        *(float4*)&pw[lane * 8 + 4] = make_float4(pv[4], pv[5], pv[6], pv[7]);
        __syncwarp();

        #pragma unroll 4
        for (int j = 0; j < 32; ++j) {
            u64 vj = *(const u64*)&vs[j * 64 + 2 * lane];
            float4 pa = *(const float4*)&pw[j * 8];
            float4 pb = *(const float4*)&pw[j * 8 + 4];
            o2[0] = fma2(pk2(pa.x, pa.x), vj, o2[0]);
            o2[1] = fma2(pk2(pa.y, pa.y), vj, o2[1]);
            o2[2] = fma2(pk2(pa.z, pa.z), vj, o2[2]);
            o2[3] = fma2(pk2(pa.w, pa.w), vj, o2[3]);
            o2[4] = fma2(pk2(pb.x, pb.x), vj, o2[4]);
            o2[5] = fma2(pk2(pb.y, pb.y), vj, o2[5]);
            o2[6] = fma2(pk2(pb.z, pb.z), vj, o2[6]);
            o2[7] = fma2(pk2(pb.w, pb.w), vj, o2[7]);
        }
        __syncwarp();
    };

    // prologue: pair 0 (chunks 0,1) into buffers {0,1}
    stage(0, 0); stage(1, 1); CP_COMMIT();

    for (int p = 0; p < 32; ++p) {
        const int b0 = 2 * (p & 1);          // buffers of pair p
        if (p < 31) {
            const int nb = 2 * ((p + 1) & 1);
            stage(nb, 2 * (p + 1));           // pair p+1 into the other
            stage(nb + 1, 2 * (p + 1) + 1);   //   buffer pair
            CP_COMMIT();
            CP_WAIT(1);
        } else {
            CP_WAIT(0);
        }
        __syncthreads();
        compute(b0);
        compute(b0 + 1);
        __syncthreads();
    }

    // ---- final l reduce + normalize + write
    #pragma unroll
    for (int r = 0; r < 8; ++r) {
        float ls = lp[r];
        #pragma unroll
        for (int o = 16; o; o >>= 1)
            ls += __shfl_xor_sync(0xffffffffu, ls, o);
        float inv = 1.f / ls;
        float lo, hi; upk2(o2[r], lo, hi);
        *(float2*)&outp[(size_t)(bt0 + r0 + r) * 512 + h * 64 + 2 * lane] =
            make_float2(lo * inv, hi * inv);
    }
}

// ---------------------------------------------------------------------------
extern "C" void kernel_launch(void* const* d_in, const int* in_sizes, int n_in,
                              void* d_out, int out_size)
{
    const float* model_embed = (const float*)d_in[0];
    const float* ctx_key     = (const float*)d_in[1];
    const float* ctx_val     = (const float*)d_in[2];
    const float* ln1w = (const float*)d_in[3];
    const float* ln1b = (const float*)d_in[4];
    const float* ln2w = (const float*)d_in[5];
    const float* ln2b = (const float*)d_in[6];
    const float* ln3w = (const float*)d_in[7];
    const float* ln3b = (const float*)d_in[8];
    const float* ln4w = (const float*)d_in[9];
    const float* ln4b = (const float*)d_in[10];
    const float* wq = (const float*)d_in[11];
    const float* bq = (const float*)d_in[12];
    const float* wk = (const float*)d_in[13];
    const float* bk = (const float*)d_in[14];
    const float* wv = (const float*)d_in[15];
    const float* bv = (const float*)d_in[16];
    const float* wo = (const float*)d_in[17];
    const float* bo = (const float*)d_in[18];
    const float* wp = (const float*)d_in[19];
    const float* bp = (const float*)d_in[20];

    float2 *stats, *stats4;
    float *q, *k, *v, *att, *o;
    cudaGetSymbolAddress((void**)&stats,  g_stats);
    cudaGetSymbolAddress((void**)&stats4, g_stats4);
    cudaGetSymbolAddress((void**)&q,    g_q);
    cudaGetSymbolAddress((void**)&k,    g_k);
    cudaGetSymbolAddress((void**)&v,    g_v);
    cudaGetSymbolAddress((void**)&att,  g_att);
    cudaGetSymbolAddress((void**)&o,    g_o);

    static int attr_set = 0;
    if (!attr_set) {
        cudaFuncSetAttribute(attn_kernel,
                             cudaFuncAttributeMaxDynamicSharedMemorySize, ATT_SMEM);
        attr_set = 1;
    }

    // zero atomic-accumulation targets for split-K
    zero2<<<1024, 256>>>(o, (float*)d_out);

    // LN stats + fused LN+GEMM projections
    ln_stats3<<<1408, 256>>>(model_embed, ctx_key, ctx_val, stats);
    sgemm_big3<<<dim3(88, 4), 256>>>(
        model_embed, stats,        ln1w, ln1b, wq, bq, q,
        ctx_key,     stats + 1024, ln2w, ln2b, wk, bk, k,
        ctx_val,     stats + 9216, ln3w, ln3b, wv, bv, v);

    // fused MaxSim attention (2 chunks per barrier period)
    attn_kernel<<<dim3(16, 8), 256, ATT_SMEM>>>(q, k, v, att);

    // output proj (split-K 2x), LN4 stats, final proj (split-K 2x, fused LN)
    sgemm_tail<<<dim3(32, 4, 2), 256>>>(att, wo, bo, o, nullptr, nullptr, nullptr, 0);
    ln_stats1<<<128, 256>>>(o, stats4);
    sgemm_tail<<<dim3(32, 4, 2), 256>>>(o, wp, bp, (float*)d_out, stats4, ln4w, ln4b, 1);
}

// round 15
// speedup vs baseline: 1.0995x; 1.0100x over previous
#include <cuda_runtime.h>
#include <cstdint>
#include <math.h>

// Shapes fixed: B=4, T=256, C=2048, U=4, D=512, P=512, H=8, dk=64

__device__ float2 g_stats[11264];   // mu/rstd for q(1024)|k(8192)|v(2048) rows
__device__ float2 g_stats4[1024];   // mu/rstd for LN4
__device__ float g_q  [1024 * 512];
__device__ float g_k  [8192 * 512];
__device__ float g_v  [2048 * 512];
__device__ float g_att[1024 * 512];
__device__ float g_o  [1024 * 512];

typedef unsigned long long u64;

__device__ __forceinline__ u64 pk2(float lo, float hi) {
    u64 r; asm("mov.b64 %0, {%1, %2};" : "=l"(r) : "f"(lo), "f"(hi)); return r;
}
__device__ __forceinline__ void upk2(u64 v, float& lo, float& hi) {
    asm("mov.b64 {%0, %1}, %2;" : "=f"(lo), "=f"(hi) : "l"(v));
}
__device__ __forceinline__ u64 fma2(u64 a, u64 b, u64 c) {
    u64 d; asm("fma.rn.f32x2 %0, %1, %2, %3;" : "=l"(d) : "l"(a), "l"(b), "l"(c)); return d;
}
__device__ __forceinline__ u64 mul2(u64 a, u64 b) {
    u64 d; asm("mul.rn.f32x2 %0, %1, %2;" : "=l"(d) : "l"(a), "l"(b)); return d;
}
__device__ __forceinline__ uint32_t smem_u32(const void* p) {
    uint32_t a;
    asm("{ .reg .u64 t; cvta.to.shared.u64 t, %1; cvt.u32.u64 %0, t; }" : "=r"(a) : "l"(p));
    return a;
}
#define CP_ASYNC16(dst, src) \
    asm volatile("cp.async.cg.shared.global [%0], [%1], 16;" :: "r"(dst), "l"(src) : "memory")
#define CP_COMMIT() asm volatile("cp.async.commit_group;" ::: "memory")
#define CP_WAIT(n)  asm volatile("cp.async.wait_group %0;" :: "n"(n) : "memory")

// ---------------------------------------------------------------------------
// LN stats: one warp per row, D=512. Writes (mu, rstd).
// ---------------------------------------------------------------------------
__device__ __forceinline__ void ln_stat_row(
    const float* __restrict__ xr, float2* __restrict__ out, int lane)
{
    float s = 0.f, ss = 0.f;
    #pragma unroll
    for (int j = 0; j < 4; ++j) {
        float4 x = *(const float4*)&xr[j * 128 + lane * 4];
        s  += x.x + x.y + x.z + x.w;
        ss += x.x * x.x + x.y * x.y + x.z * x.z + x.w * x.w;
    }
    #pragma unroll
    for (int o = 16; o; o >>= 1) {
        s  += __shfl_xor_sync(0xffffffffu, s, o);
        ss += __shfl_xor_sync(0xffffffffu, ss, o);
    }
    if (lane == 0) {
        float mu = s * (1.f / 512.f);
        float rstd = rsqrtf(ss * (1.f / 512.f) - mu * mu + 1e-5f);
        *out = make_float2(mu, rstd);
    }
}

// Batched LN stats for q/k/v inputs; also zeroes the two atomic targets
// (g_o, d_out: 262144 float4 total) using the same 1408-block launch.
__global__ __launch_bounds__(256) void ln_stats3(
    const float* __restrict__ x0, const float* __restrict__ x1,
    const float* __restrict__ x2, float2* __restrict__ st,
    float* __restrict__ z0, float* __restrict__ z1)
{
    const int lane = threadIdx.x & 31;
    const int wr = threadIdx.x >> 5;
    const int bx = blockIdx.x;

    // zeroing: global thread idx < 262144 handles one float4
    int zi = bx * 256 + threadIdx.x;
    if (zi < 131072)
        *(float4*)&z0[zi * 4] = make_float4(0.f, 0.f, 0.f, 0.f);
    else if (zi < 262144)
        *(float4*)&z1[(zi - 131072) * 4] = make_float4(0.f, 0.f, 0.f, 0.f);

    const float* x; size_t row; float2* o;
    if (bx < 128)       { x = x0; row = (size_t)bx * 8 + wr; o = st; }
    else if (bx < 1152) { x = x1; row = (size_t)(bx - 128) * 8 + wr; o = st + 1024; }
    else                { x = x2; row = (size_t)(bx - 1152) * 8 + wr; o = st + 9216; }
    ln_stat_row(x + row * 512, o + row, lane);
}

__global__ __launch_bounds__(256) void ln_stats1(
    const float* __restrict__ x, float2* __restrict__ st)
{
    const int lane = threadIdx.x & 31;
    const size_t row = (size_t)blockIdx.x * 8 + (threadIdx.x >> 5);
    ln_stat_row(x + row * 512, st + row, lane);
}

// ---------------------------------------------------------------------------
// sgemm_big with fused LN on A-load: 128x128 tile, BK=16, 256 thr, 8x8 tile.
// ---------------------------------------------------------------------------
__device__ __forceinline__ void sgemm_big_body_ln(
    const float* __restrict__ A, const float2* __restrict__ stats,
    const float* __restrict__ lnw, const float* __restrict__ lnb,
    const float* __restrict__ B, const float* __restrict__ bias,
    float* __restrict__ C, size_t m0, int n0)
{
    __shared__ float As[2][16][132];
    __shared__ float Bs[2][16][132];

    const int tid = threadIdx.x;
    const int ty = tid >> 4, tx = tid & 15;
    const int ar = tid >> 1, ak4 = (tid & 1) * 8;
    const int bk = tid >> 4, bn = (tid & 15) * 8;

    const float2 st = stats[m0 + ar];

    u64 acc[8][4];
    #pragma unroll
    for (int i = 0; i < 8; ++i)
        #pragma unroll
        for (int j = 0; j < 4; ++j) acc[i][j] = 0ull;

    float4 la0, la1, lb0, lb1;
    {
        float4 r0 = *(const float4*)&A[(m0 + ar) * 512 + ak4];
        float4 r1 = *(const float4*)&A[(m0 + ar) * 512 + ak4 + 4];
        float4 w0 = *(const float4*)&lnw[ak4];
        float4 w1 = *(const float4*)&lnw[ak4 + 4];
        float4 b0 = *(const float4*)&lnb[ak4];
        float4 b1 = *(const float4*)&lnb[ak4 + 4];
        la0.x = (r0.x - st.x) * st.y * w0.x + b0.x;
        la0.y = (r0.y - st.x) * st.y * w0.y + b0.y;
        la0.z = (r0.z - st.x) * st.y * w0.z + b0.z;
        la0.w = (r0.w - st.x) * st.y * w0.w + b0.w;
        la1.x = (r1.x - st.x) * st.y * w1.x + b1.x;
        la1.y = (r1.y - st.x) * st.y * w1.y + b1.y;
        la1.z = (r1.z - st.x) * st.y * w1.z + b1.z;
        la1.w = (r1.w - st.x) * st.y * w1.w + b1.w;
    }
    lb0 = *(const float4*)&B[(size_t)bk * 512 + n0 + bn];
    lb1 = *(const float4*)&B[(size_t)bk * 512 + n0 + bn + 4];
    {
        As[0][ak4 + 0][ar] = la0.x; As[0][ak4 + 1][ar] = la0.y;
        As[0][ak4 + 2][ar] = la0.z; As[0][ak4 + 3][ar] = la0.w;
        As[0][ak4 + 4][ar] = la1.x; As[0][ak4 + 5][ar] = la1.y;
        As[0][ak4 + 6][ar] = la1.z; As[0][ak4 + 7][ar] = la1.w;
        *(float4*)&Bs[0][bk][bn]     = lb0;
        *(float4*)&Bs[0][bk][bn + 4] = lb1;
    }
    __syncthreads();

    for (int kt = 0; kt < 32; ++kt) {
        const int buf = kt & 1;
        if (kt < 31) {
            const int k0 = (kt + 1) * 16;
            float4 r0 = *(const float4*)&A[(m0 + ar) * 512 + k0 + ak4];
            float4 r1 = *(const float4*)&A[(m0 + ar) * 512 + k0 + ak4 + 4];
            float4 w0 = *(const float4*)&lnw[k0 + ak4];
            float4 w1 = *(const float4*)&lnw[k0 + ak4 + 4];
            float4 b0 = *(const float4*)&lnb[k0 + ak4];
            float4 b1 = *(const float4*)&lnb[k0 + ak4 + 4];
            la0.x = (r0.x - st.x) * st.y * w0.x + b0.x;
            la0.y = (r0.y - st.x) * st.y * w0.y + b0.y;
            la0.z = (r0.z - st.x) * st.y * w0.z + b0.z;
            la0.w = (r0.w - st.x) * st.y * w0.w + b0.w;
            la1.x = (r1.x - st.x) * st.y * w1.x + b1.x;
            la1.y = (r1.y - st.x) * st.y * w1.y + b1.y;
            la1.z = (r1.z - st.x) * st.y * w1.z + b1.z;
            la1.w = (r1.w - st.x) * st.y * w1.w + b1.w;
            lb0 = *(const float4*)&B[(size_t)(k0 + bk) * 512 + n0 + bn];
            lb1 = *(const float4*)&B[(size_t)(k0 + bk) * 512 + n0 + bn + 4];
        }
        #pragma unroll
        for (int kk = 0; kk < 16; ++kk) {
            float4 a0 = *(const float4*)&As[buf][kk][ty * 8];
            float4 a1 = *(const float4*)&As[buf][kk][ty * 8 + 4];
            u64 b0 = *(const u64*)&Bs[buf][kk][2 * tx];
            u64 b1 = *(const u64*)&Bs[buf][kk][2 * tx + 32];
            u64 b2 = *(const u64*)&Bs[buf][kk][2 * tx + 64];
            u64 b3 = *(const u64*)&Bs[buf][kk][2 * tx + 96];
            float av[8] = {a0.x, a0.y, a0.z, a0.w, a1.x, a1.y, a1.z, a1.w};
            #pragma unroll
            for (int i = 0; i < 8; ++i) {
                u64 ai = pk2(av[i], av[i]);
                acc[i][0] = fma2(ai, b0, acc[i][0]);
                acc[i][1] = fma2(ai, b1, acc[i][1]);
                acc[i][2] = fma2(ai, b2, acc[i][2]);
                acc[i][3] = fma2(ai, b3, acc[i][3]);
            }
        }
        if (kt < 31) {
            const int nb = 1 - buf;
            As[nb][ak4 + 0][ar] = la0.x; As[nb][ak4 + 1][ar] = la0.y;
            As[nb][ak4 + 2][ar] = la0.z; As[nb][ak4 + 3][ar] = la0.w;
            As[nb][ak4 + 4][ar] = la1.x; As[nb][ak4 + 5][ar] = la1.y;
            As[nb][ak4 + 6][ar] = la1.z; As[nb][ak4 + 7][ar] = la1.w;
            *(float4*)&Bs[nb][bk][bn]     = lb0;
            *(float4*)&Bs[nb][bk][bn + 4] = lb1;
        }
        __syncthreads();
    }

    #pragma unroll
    for (int j = 0; j < 4; ++j) {
        const int col = n0 + 2 * tx + 32 * j;
        float2 bb = *(const float2*)&bias[col];
        #pragma unroll
        for (int i = 0; i < 8; ++i) {
            float o0, o1; upk2(acc[i][j], o0, o1);
            *(float2*)&C[(m0 + ty * 8 + i) * 512 + col] =
                make_float2(o0 + bb.x, o1 + bb.y);
        }
    }
}

__global__ __launch_bounds__(256) void sgemm_big3(
    const float* __restrict__ Aq, const float2* __restrict__ Sq, const float* __restrict__ W1q, const float* __restrict__ B1q, const float* __restrict__ Wq, const float* __restrict__ Bq, float* __restrict__ Cq,
    const float* __restrict__ Ak, const float2* __restrict__ Sk, const float* __restrict__ W1k, const float* __restrict__ B1k, const float* __restrict__ Wk, const float* __restrict__ Bk, float* __restrict__ Ck,
    const float* __restrict__ Av, const float2* __restrict__ Sv, const float* __restrict__ W1v, const float* __restrict__ B1v, const float* __restrict__ Wv, const float* __restrict__ Bv, float* __restrict__ Cv)
{
    const int bx = blockIdx.x;
    const int n0 = blockIdx.y * 128;
    if (bx < 8)
        sgemm_big_body_ln(Aq, Sq, W1q, B1q, Wq, Bq, Cq, (size_t)bx * 128, n0);
    else if (bx < 72)
        sgemm_big_body_ln(Ak, Sk, W1k, B1k, Wk, Bk, Ck, (size_t)(bx - 8) * 128, n0);
    else
        sgemm_big_body_ln(Av, Sv, W1v, B1v, Wv, Bv, Cv, (size_t)(bx - 72) * 128, n0);
}

// ---------------------------------------------------------------------------
// Tail GEMM, 2-way split-K with atomic accumulation into pre-zeroed C.
// 32x128 tile, 256 threads, 2x8 thread tile, optional fused LN.
// grid (M/32, 4, 2); blockIdx.z = K half. Split 0 adds bias.
// ---------------------------------------------------------------------------
__global__ __launch_bounds__(256) void sgemm_tail(
    const float* __restrict__ A, const float* __restrict__ B,
    const float* __restrict__ bias, float* __restrict__ C,
    const float2* __restrict__ stats, const float* __restrict__ lnw,
    const float* __restrict__ lnb, int do_ln)
{
    __shared__ float As[2][16][36];
    __shared__ float Bs[2][16][132];

    const int tid = threadIdx.x;
    const int ty = tid >> 4;
    const int tx = tid & 15;
    const size_t m0 = (size_t)blockIdx.x * 32;
    const int n0 = blockIdx.y * 128;
    const int kbase = blockIdx.z * 256;

    const int ar  = tid >> 2;
    const int ak4 = (tid & 3) * 4;
    const int bk  = tid >> 4;
    const int bn  = (tid & 15) * 8;
    const bool aload = tid < 128;

    float2 st = make_float2(0.f, 1.f);
    if (do_ln && aload) st = stats[m0 + ar];

    u64 acc[2][4];
    #pragma unroll
    for (int i = 0; i < 2; ++i)
        #pragma unroll
        for (int j = 0; j < 4; ++j) acc[i][j] = 0ull;

    float4 la = make_float4(0, 0, 0, 0);
    float4 lb0, lb1;
    if (aload) {
        float4 r = *(const float4*)&A[(m0 + ar) * 512 + kbase + ak4];
        if (do_ln) {
            float4 w = *(const float4*)&lnw[kbase + ak4];
            float4 b = *(const float4*)&lnb[kbase + ak4];
            la.x = (r.x - st.x) * st.y * w.x + b.x;
            la.y = (r.y - st.x) * st.y * w.y + b.y;
            la.z = (r.z - st.x) * st.y * w.z + b.z;
            la.w = (r.w - st.x) * st.y * w.w + b.w;
        } else la = r;
    }
    lb0 = *(const float4*)&B[(size_t)(kbase + bk) * 512 + n0 + bn];
    lb1 = *(const float4*)&B[(size_t)(kbase + bk) * 512 + n0 + bn + 4];
    if (aload) {
        As[0][ak4 + 0][ar] = la.x; As[0][ak4 + 1][ar] = la.y;
        As[0][ak4 + 2][ar] = la.z; As[0][ak4 + 3][ar] = la.w;
    }
    *(float4*)&Bs[0][bk][bn]     = lb0;
    *(float4*)&Bs[0][bk][bn + 4] = lb1;
    __syncthreads();

    for (int kt = 0; kt < 16; ++kt) {
        const int buf = kt & 1;
        if (kt < 15) {
            const int k0 = kbase + (kt + 1) * 16;
            if (aload) {
                float4 r = *(const float4*)&A[(m0 + ar) * 512 + k0 + ak4];
                if (do_ln) {
                    float4 w = *(const float4*)&lnw[k0 + ak4];
                    float4 b = *(const float4*)&lnb[k0 + ak4];
                    la.x = (r.x - st.x) * st.y * w.x + b.x;
                    la.y = (r.y - st.x) * st.y * w.y + b.y;
                    la.z = (r.z - st.x) * st.y * w.z + b.z;
                    la.w = (r.w - st.x) * st.y * w.w + b.w;
                } else la = r;
            }
            lb0 = *(const float4*)&B[(size_t)(k0 + bk) * 512 + n0 + bn];
            lb1 = *(const float4*)&B[(size_t)(k0 + bk) * 512 + n0 + bn + 4];
        }
        #pragma unroll
        for (int kk = 0; kk < 16; ++kk) {
            float2 a = *(const float2*)&As[buf][kk][ty * 2];
            u64 b0 = *(const u64*)&Bs[buf][kk][2 * tx];
            u64 b1 = *(const u64*)&Bs[buf][kk][2 * tx + 32];
            u64 b2 = *(const u64*)&Bs[buf][kk][2 * tx + 64];
            u64 b3 = *(const u64*)&Bs[buf][kk][2 * tx + 96];
            u64 a0 = pk2(a.x, a.x), a1 = pk2(a.y, a.y);
            acc[0][0] = fma2(a0, b0, acc[0][0]);
            acc[0][1] = fma2(a0, b1, acc[0][1]);
            acc[0][2] = fma2(a0, b2, acc[0][2]);
            acc[0][3] = fma2(a0, b3, acc[0][3]);
            acc[1][0] = fma2(a1, b0, acc[1][0]);
            acc[1][1] = fma2(a1, b1, acc[1][1]);
            acc[1][2] = fma2(a1, b2, acc[1][2]);
            acc[1][3] = fma2(a1, b3, acc[1][3]);
        }
        if (kt < 15) {
            const int nb = 1 - buf;
            if (aload) {
                As[nb][ak4 + 0][ar] = la.x; As[nb][ak4 + 1][ar] = la.y;
                As[nb][ak4 + 2][ar] = la.z; As[nb][ak4 + 3][ar] = la.w;
            }
            *(float4*)&Bs[nb][bk][bn]     = lb0;
            *(float4*)&Bs[nb][bk][bn + 4] = lb1;
        }
        __syncthreads();
    }

    const bool addb = (blockIdx.z == 0);
    #pragma unroll
    for (int j = 0; j < 4; ++j) {
        const int col = n0 + 2 * tx + 32 * j;
        float2 bb = addb ? *(const float2*)&bias[col] : make_float2(0.f, 0.f);
        #pragma unroll
        for (int i = 0; i < 2; ++i) {
            float o0, o1; upk2(acc[i][j], o0, o1);
            float* cp = &C[(m0 + ty * 2 + i) * 512 + col];
            atomicAdd(cp,     o0 + bb.x);
            atomicAdd(cp + 1, o1 + bb.y);
        }
    }
}

// ---------------------------------------------------------------------------
// Fused ColBERT attention (R14, best measured). Block 256 thr / 8 warps,
// grid (16, 8). 64-token tile, 8 rows/warp, 2 chunks per barrier period
// with 4 K/V buffers. Per-lane l, pk2-AV, Q pre-scaled.
// smem floats: qs[4096] | ks 4x[8192] | vs 4x[2048] | pd[2048] = 47104
// ---------------------------------------------------------------------------
#define ATT_SMEM (47104 * 4)

__global__ __launch_bounds__(256) void attn_kernel(
    const float* __restrict__ q, const float* __restrict__ k,
    const float* __restrict__ v, float* __restrict__ outp)
{
    extern __shared__ float sm[];
    float* qs  = sm;             // [64][64], pre-scaled by 0.125
    float* ksb = sm + 4096;      // 4 x [u][cc][64] swizzled
    float* vsb = sm + 36864;     // 4 x [cc][64]
    float* pd  = sm + 45056;     // [warp][cc][8]

    const int tid  = threadIdx.x;
    const int w    = tid >> 5;
    const int lane = tid & 31;
    const int h    = blockIdx.y;
    const int bt0  = blockIdx.x * 64;
    const int r0   = w * 8;
    const int sw   = (lane & 7) << 2;
    const uint32_t smb = smem_u32(sm);

    const int scc = tid >> 3, srr = tid & 7;
    const float* kg = k + ((size_t)scc * 4) * 512 + h * 64 + srr * 4;
    const uint32_t koff0 = (uint32_t)(scc * 64 + ((srr * 4) ^ ((scc & 7) << 2)));
    const float* vg = v + (size_t)(tid >> 4) * 512 + h * 64 + (tid & 15) * 4;
    const uint32_t voff0 = (uint32_t)((tid >> 4) * 64 + (tid & 15) * 4);

    // Q staging with 1/8 scale folded in: 1024 float4
    #pragma unroll
    for (int j = 0; j < 4; ++j) {
        int i = tid + 256 * j;
        int dd = i & 15, r = i >> 4;
        float4 t = *(const float4*)&q[(size_t)(bt0 + r) * 512 + h * 64 + dd * 4];
        *(float4*)&qs[r * 64 + dd * 4] =
            make_float4(t.x * 0.125f, t.y * 0.125f, t.z * 0.125f, t.w * 0.125f);
    }

    auto stage = [&](int b, int c) {
        const float* kp = kg + (size_t)c * 65536;
        const uint32_t kd = smb + (4096 + b * 8192 + koff0) * 4;
        #pragma unroll
        for (int j = 0; j < 8; ++j)
            CP_ASYNC16(kd + (uint32_t)(((j & 1) * 32 + (j >> 1) * 2048) * 4),
                       kp + (j >> 1) * 512 + (j & 1) * 32);
        const float* vp = vg + (size_t)c * 16384;
        const uint32_t vd = smb + (36864 + b * 2048 + voff0) * 4;
        CP_ASYNC16(vd, vp);
        CP_ASYNC16(vd + 1024 * 4, vp + 8192);
    };

    float m[8], lp[8];          // lp = per-lane partial denominator
    u64 o2[8];
    #pragma unroll
    for (int r = 0; r < 8; ++r) { m[r] = -1e30f; lp[r] = 0.f; o2[r] = 0ull; }

    float* pw = pd + w * 256;

    auto compute = [&](int buf) {
        const float* ks = ksb + buf * 8192;
        const float* vs = vsb + buf * 2048;
        const float* kb = ks + lane * 64;

        u64 acc[8][4];
        #pragma unroll
        for (int r = 0; r < 8; ++r)
            #pragma unroll
            for (int u = 0; u < 4; ++u) acc[r][u] = 0ull;

        #pragma unroll
        for (int d4 = 0; d4 < 64; d4 += 4) {
            const int off = d4 ^ sw;
            ulonglong2 k0 = *(const ulonglong2*)&kb[off];
            ulonglong2 k1 = *(const ulonglong2*)&kb[off + 2048];
            ulonglong2 k2 = *(const ulonglong2*)&kb[off + 4096];
            ulonglong2 k3 = *(const ulonglong2*)&kb[off + 6144];
            #pragma unroll
            for (int r = 0; r < 8; ++r) {
                ulonglong2 qq = *(const ulonglong2*)&qs[(r0 + r) * 64 + d4];
                acc[r][0] = fma2(qq.x, k0.x, acc[r][0]);
                acc[r][0] = fma2(qq.y, k0.y, acc[r][0]);
                acc[r][1] = fma2(qq.x, k1.x, acc[r][1]);
                acc[r][1] = fma2(qq.y, k1.y, acc[r][1]);
                acc[r][2] = fma2(qq.x, k2.x, acc[r][2]);
                acc[r][2] = fma2(qq.y, k2.y, acc[r][2]);
                acc[r][3] = fma2(qq.x, k3.x, acc[r][3]);
                acc[r][3] = fma2(qq.y, k3.y, acc[r][3]);
            }
        }

        float pv[8];
        #pragma unroll
        for (int r = 0; r < 8; ++r) {
            float x0, x1, s;
            upk2(acc[r][0], x0, x1); s = x0 + x1;
            upk2(acc[r][1], x0, x1); s = fmaxf(s, x0 + x1);
            upk2(acc[r][2], x0, x1); s = fmaxf(s, x0 + x1);
            upk2(acc[r][3], x0, x1); s = fmaxf(s, x0 + x1);
            float cm = s;
            #pragma unroll
            for (int o = 16; o; o >>= 1)
                cm = fmaxf(cm, __shfl_xor_sync(0xffffffffu, cm, o));
            float mn   = fmaxf(m[r], cm);
            float corr = __expf(m[r] - mn);
            pv[r] = __expf(s - mn);
            lp[r] = lp[r] * corr + pv[r];
            m[r] = mn;
            o2[r] = mul2(o2[r], pk2(corr, corr));
        }

        *(float4*)&pw[lane * 8]     = make_float4(pv[0], pv[1], pv[2], pv[3]);
        *(float4*)&pw[lane * 8 + 4] = make_float4(pv[4], pv[5], pv[6], pv[7]);
        __syncwarp();

        #pragma unroll
        for (int j = 0; j < 32; ++j) {
            u64 vj = *(const u64*)&vs[j * 64 + 2 * lane];
            float4 pa = *(const float4*)&pw[j * 8];
            float4 pb = *(const float4*)&pw[j * 8 + 4];
            o2[0] = fma2(pk2(pa.x, pa.x), vj, o2[0]);
            o2[1] = fma2(pk2(pa.y, pa.y), vj, o2[1]);
            o2[2] = fma2(pk2(pa.z, pa.z), vj, o2[2]);
            o2[3] = fma2(pk2(pa.w, pa.w), vj, o2[3]);
            o2[4] = fma2(pk2(pb.x, pb.x), vj, o2[4]);
            o2[5] = fma2(pk2(pb.y, pb.y), vj, o2[5]);
            o2[6] = fma2(pk2(pb.z, pb.z), vj, o2[6]);
            o2[7] = fma2(pk2(pb.w, pb.w), vj, o2[7]);
        }
        __syncwarp();
    };

    // prologue: pair 0 (chunks 0,1) into buffers {0,1}
    stage(0, 0); stage(1, 1); CP_COMMIT();

    for (int p = 0; p < 32; ++p) {
        const int b0 = 2 * (p & 1);
        if (p < 31) {
            const int nb = 2 * ((p + 1) & 1);
            stage(nb, 2 * (p + 1));
            stage(nb + 1, 2 * (p + 1) + 1);
            CP_COMMIT();
            CP_WAIT(1);
        } else {
            CP_WAIT(0);
        }
        __syncthreads();
        compute(b0);
        compute(b0 + 1);
        __syncthreads();
    }

    // ---- final l reduce + normalize + write
    #pragma unroll
    for (int r = 0; r < 8; ++r) {
        float ls = lp[r];
        #pragma unroll
        for (int o = 16; o; o >>= 1)
            ls += __shfl_xor_sync(0xffffffffu, ls, o);
        float inv = 1.f / ls;
        float lo, hi; upk2(o2[r], lo, hi);
        *(float2*)&outp[(size_t)(bt0 + r0 + r) * 512 + h * 64 + 2 * lane] =
            make_float2(lo * inv, hi * inv);
    }
}

// ---------------------------------------------------------------------------
extern "C" void kernel_launch(void* const* d_in, const int* in_sizes, int n_in,
                              void* d_out, int out_size)
{
    const float* model_embed = (const float*)d_in[0];
    const float* ctx_key     = (const float*)d_in[1];
    const float* ctx_val     = (const float*)d_in[2];
    const float* ln1w = (const float*)d_in[3];
    const float* ln1b = (const float*)d_in[4];
    const float* ln2w = (const float*)d_in[5];
    const float* ln2b = (const float*)d_in[6];
    const float* ln3w = (const float*)d_in[7];
    const float* ln3b = (const float*)d_in[8];
    const float* ln4w = (const float*)d_in[9];
    const float* ln4b = (const float*)d_in[10];
    const float* wq = (const float*)d_in[11];
    const float* bq = (const float*)d_in[12];
    const float* wk = (const float*)d_in[13];
    const float* bk = (const float*)d_in[14];
    const float* wv = (const float*)d_in[15];
    const float* bv = (const float*)d_in[16];
    const float* wo = (const float*)d_in[17];
    const float* bo = (const float*)d_in[18];
    const float* wp = (const float*)d_in[19];
    const float* bp = (const float*)d_in[20];

    float2 *stats, *stats4;
    float *q, *k, *v, *att, *o;
    cudaGetSymbolAddress((void**)&stats,  g_stats);
    cudaGetSymbolAddress((void**)&stats4, g_stats4);
    cudaGetSymbolAddress((void**)&q,    g_q);
    cudaGetSymbolAddress((void**)&k,    g_k);
    cudaGetSymbolAddress((void**)&v,    g_v);
    cudaGetSymbolAddress((void**)&att,  g_att);
    cudaGetSymbolAddress((void**)&o,    g_o);

    static int attr_set = 0;
    if (!attr_set) {
        cudaFuncSetAttribute(attn_kernel,
                             cudaFuncAttributeMaxDynamicSharedMemorySize, ATT_SMEM);
        attr_set = 1;
    }

    // LN stats (+ fused zeroing of atomic targets) + LN+GEMM projections
    ln_stats3<<<1408, 256>>>(model_embed, ctx_key, ctx_val, stats,
                             o, (float*)d_out);
    sgemm_big3<<<dim3(88, 4), 256>>>(
        model_embed, stats,        ln1w, ln1b, wq, bq, q,
        ctx_key,     stats + 1024, ln2w, ln2b, wk, bk, k,
        ctx_val,     stats + 9216, ln3w, ln3b, wv, bv, v);

    // fused MaxSim attention
    attn_kernel<<<dim3(16, 8), 256, ATT_SMEM>>>(q, k, v, att);

    // output proj (split-K 2x), LN4 stats, final proj (split-K 2x, fused LN)
    sgemm_tail<<<dim3(32, 4, 2), 256>>>(att, wo, bo, o, nullptr, nullptr, nullptr, 0);
    ln_stats1<<<128, 256>>>(o, stats4);
    sgemm_tail<<<dim3(32, 4, 2), 256>>>(o, wp, bp, (float*)d_out, stats4, ln4w, ln4b, 1);
}

// round 16
// speedup vs baseline: 1.1013x; 1.0016x over previous
#include <cuda_runtime.h>
#include <cstdint>
#include <math.h>

// Shapes fixed: B=4, T=256, C=2048, U=4, D=512, P=512, H=8, dk=64

__device__ float2 g_stats[11264];   // mu/rstd for q(1024)|k(8192)|v(2048) rows
__device__ float2 g_stats4[1024];   // mu/rstd for LN4
__device__ float g_q  [1024 * 512];
__device__ float g_k  [8192 * 512];
__device__ float g_v  [2048 * 512];
__device__ float g_att[1024 * 512];
__device__ float g_o  [1024 * 512];

typedef unsigned long long u64;

__device__ __forceinline__ u64 pk2(float lo, float hi) {
    u64 r; asm("mov.b64 %0, {%1, %2};" : "=l"(r) : "f"(lo), "f"(hi)); return r;
}
__device__ __forceinline__ void upk2(u64 v, float& lo, float& hi) {
    asm("mov.b64 {%0, %1}, %2;" : "=f"(lo), "=f"(hi) : "l"(v));
}
__device__ __forceinline__ u64 fma2(u64 a, u64 b, u64 c) {
    u64 d; asm("fma.rn.f32x2 %0, %1, %2, %3;" : "=l"(d) : "l"(a), "l"(b), "l"(c)); return d;
}
__device__ __forceinline__ u64 mul2(u64 a, u64 b) {
    u64 d; asm("mul.rn.f32x2 %0, %1, %2;" : "=l"(d) : "l"(a), "l"(b)); return d;
}
__device__ __forceinline__ uint32_t smem_u32(const void* p) {
    uint32_t a;
    asm("{ .reg .u64 t; cvta.to.shared.u64 t, %1; cvt.u32.u64 %0, t; }" : "=r"(a) : "l"(p));
    return a;
}
#define CP_ASYNC16(dst, src) \
    asm volatile("cp.async.cg.shared.global [%0], [%1], 16;" :: "r"(dst), "l"(src) : "memory")
#define CP_COMMIT() asm volatile("cp.async.commit_group;" ::: "memory")
#define CP_WAIT(n)  asm volatile("cp.async.wait_group %0;" :: "n"(n) : "memory")

// ---------------------------------------------------------------------------
// LN stats: one warp per row, D=512. Writes (mu, rstd).
// ---------------------------------------------------------------------------
__device__ __forceinline__ void ln_stat_row(
    const float* __restrict__ xr, float2* __restrict__ out, int lane)
{
    float s = 0.f, ss = 0.f;
    #pragma unroll
    for (int j = 0; j < 4; ++j) {
        float4 x = *(const float4*)&xr[j * 128 + lane * 4];
        s  += x.x + x.y + x.z + x.w;
        ss += x.x * x.x + x.y * x.y + x.z * x.z + x.w * x.w;
    }
    #pragma unroll
    for (int o = 16; o; o >>= 1) {
        s  += __shfl_xor_sync(0xffffffffu, s, o);
        ss += __shfl_xor_sync(0xffffffffu, ss, o);
    }
    if (lane == 0) {
        float mu = s * (1.f / 512.f);
        float rstd = rsqrtf(ss * (1.f / 512.f) - mu * mu + 1e-5f);
        *out = make_float2(mu, rstd);
    }
}

// Batched LN stats for q/k/v inputs; also zeroes the two atomic targets
// (g_o, d_out: 262144 float4 total) using the same 1408-block launch.
__global__ __launch_bounds__(256) void ln_stats3(
    const float* __restrict__ x0, const float* __restrict__ x1,
    const float* __restrict__ x2, float2* __restrict__ st,
    float* __restrict__ z0, float* __restrict__ z1)
{
    const int lane = threadIdx.x & 31;
    const int wr = threadIdx.x >> 5;
    const int bx = blockIdx.x;

    // zeroing: global thread idx < 262144 handles one float4
    int zi = bx * 256 + threadIdx.x;
    if (zi < 131072)
        *(float4*)&z0[zi * 4] = make_float4(0.f, 0.f, 0.f, 0.f);
    else if (zi < 262144)
        *(float4*)&z1[(zi - 131072) * 4] = make_float4(0.f, 0.f, 0.f, 0.f);

    const float* x; size_t row; float2* o;
    if (bx < 128)       { x = x0; row = (size_t)bx * 8 + wr; o = st; }
    else if (bx < 1152) { x = x1; row = (size_t)(bx - 128) * 8 + wr; o = st + 1024; }
    else                { x = x2; row = (size_t)(bx - 1152) * 8 + wr; o = st + 9216; }
    ln_stat_row(x + row * 512, o + row, lane);
}

__global__ __launch_bounds__(256) void ln_stats1(
    const float* __restrict__ x, float2* __restrict__ st)
{
    const int lane = threadIdx.x & 31;
    const size_t row = (size_t)blockIdx.x * 8 + (threadIdx.x >> 5);
    ln_stat_row(x + row * 512, st + row, lane);
}

// ---------------------------------------------------------------------------
// sgemm_big with fused LN on A-load: 128x128 tile, BK=16, 256 thr, 8x8 tile.
// ---------------------------------------------------------------------------
__device__ __forceinline__ void sgemm_big_body_ln(
    const float* __restrict__ A, const float2* __restrict__ stats,
    const float* __restrict__ lnw, const float* __restrict__ lnb,
    const float* __restrict__ B, const float* __restrict__ bias,
    float* __restrict__ C, size_t m0, int n0)
{
    __shared__ float As[2][16][132];
    __shared__ float Bs[2][16][132];

    const int tid = threadIdx.x;
    const int ty = tid >> 4, tx = tid & 15;
    const int ar = tid >> 1, ak4 = (tid & 1) * 8;
    const int bk = tid >> 4, bn = (tid & 15) * 8;

    const float2 st = stats[m0 + ar];

    u64 acc[8][4];
    #pragma unroll
    for (int i = 0; i < 8; ++i)
        #pragma unroll
        for (int j = 0; j < 4; ++j) acc[i][j] = 0ull;

    float4 la0, la1, lb0, lb1;
    {
        float4 r0 = *(const float4*)&A[(m0 + ar) * 512 + ak4];
        float4 r1 = *(const float4*)&A[(m0 + ar) * 512 + ak4 + 4];
        float4 w0 = *(const float4*)&lnw[ak4];
        float4 w1 = *(const float4*)&lnw[ak4 + 4];
        float4 b0 = *(const float4*)&lnb[ak4];
        float4 b1 = *(const float4*)&lnb[ak4 + 4];
        la0.x = (r0.x - st.x) * st.y * w0.x + b0.x;
        la0.y = (r0.y - st.x) * st.y * w0.y + b0.y;
        la0.z = (r0.z - st.x) * st.y * w0.z + b0.z;
        la0.w = (r0.w - st.x) * st.y * w0.w + b0.w;
        la1.x = (r1.x - st.x) * st.y * w1.x + b1.x;
        la1.y = (r1.y - st.x) * st.y * w1.y + b1.y;
        la1.z = (r1.z - st.x) * st.y * w1.z + b1.z;
        la1.w = (r1.w - st.x) * st.y * w1.w + b1.w;
    }
    lb0 = *(const float4*)&B[(size_t)bk * 512 + n0 + bn];
    lb1 = *(const float4*)&B[(size_t)bk * 512 + n0 + bn + 4];
    {
        As[0][ak4 + 0][ar] = la0.x; As[0][ak4 + 1][ar] = la0.y;
        As[0][ak4 + 2][ar] = la0.z; As[0][ak4 + 3][ar] = la0.w;
        As[0][ak4 + 4][ar] = la1.x; As[0][ak4 + 5][ar] = la1.y;
        As[0][ak4 + 6][ar] = la1.z; As[0][ak4 + 7][ar] = la1.w;
        *(float4*)&Bs[0][bk][bn]     = lb0;
        *(float4*)&Bs[0][bk][bn + 4] = lb1;
    }
    __syncthreads();

    for (int kt = 0; kt < 32; ++kt) {
        const int buf = kt & 1;
        if (kt < 31) {
            const int k0 = (kt + 1) * 16;
            float4 r0 = *(const float4*)&A[(m0 + ar) * 512 + k0 + ak4];
            float4 r1 = *(const float4*)&A[(m0 + ar) * 512 + k0 + ak4 + 4];
            float4 w0 = *(const float4*)&lnw[k0 + ak4];
            float4 w1 = *(const float4*)&lnw[k0 + ak4 + 4];
            float4 b0 = *(const float4*)&lnb[k0 + ak4];
            float4 b1 = *(const float4*)&lnb[k0 + ak4 + 4];
            la0.x = (r0.x - st.x) * st.y * w0.x + b0.x;
            la0.y = (r0.y - st.x) * st.y * w0.y + b0.y;
            la0.z = (r0.z - st.x) * st.y * w0.z + b0.z;
            la0.w = (r0.w - st.x) * st.y * w0.w + b0.w;
            la1.x = (r1.x - st.x) * st.y * w1.x + b1.x;
            la1.y = (r1.y - st.x) * st.y * w1.y + b1.y;
            la1.z = (r1.z - st.x) * st.y * w1.z + b1.z;
            la1.w = (r1.w - st.x) * st.y * w1.w + b1.w;
            lb0 = *(const float4*)&B[(size_t)(k0 + bk) * 512 + n0 + bn];
            lb1 = *(const float4*)&B[(size_t)(k0 + bk) * 512 + n0 + bn + 4];
        }
        #pragma unroll
        for (int kk = 0; kk < 16; ++kk) {
            float4 a0 = *(const float4*)&As[buf][kk][ty * 8];
            float4 a1 = *(const float4*)&As[buf][kk][ty * 8 + 4];
            u64 b0 = *(const u64*)&Bs[buf][kk][2 * tx];
            u64 b1 = *(const u64*)&Bs[buf][kk][2 * tx + 32];
            u64 b2 = *(const u64*)&Bs[buf][kk][2 * tx + 64];
            u64 b3 = *(const u64*)&Bs[buf][kk][2 * tx + 96];
            float av[8] = {a0.x, a0.y, a0.z, a0.w, a1.x, a1.y, a1.z, a1.w};
            #pragma unroll
            for (int i = 0; i < 8; ++i) {
                u64 ai = pk2(av[i], av[i]);
                acc[i][0] = fma2(ai, b0, acc[i][0]);
                acc[i][1] = fma2(ai, b1, acc[i][1]);
                acc[i][2] = fma2(ai, b2, acc[i][2]);
                acc[i][3] = fma2(ai, b3, acc[i][3]);
            }
        }
        if (kt < 31) {
            const int nb = 1 - buf;
            As[nb][ak4 + 0][ar] = la0.x; As[nb][ak4 + 1][ar] = la0.y;
            As[nb][ak4 + 2][ar] = la0.z; As[nb][ak4 + 3][ar] = la0.w;
            As[nb][ak4 + 4][ar] = la1.x; As[nb][ak4 + 5][ar] = la1.y;
            As[nb][ak4 + 6][ar] = la1.z; As[nb][ak4 + 7][ar] = la1.w;
            *(float4*)&Bs[nb][bk][bn]     = lb0;
            *(float4*)&Bs[nb][bk][bn + 4] = lb1;
        }
        __syncthreads();
    }

    #pragma unroll
    for (int j = 0; j < 4; ++j) {
        const int col = n0 + 2 * tx + 32 * j;
        float2 bb = *(const float2*)&bias[col];
        #pragma unroll
        for (int i = 0; i < 8; ++i) {
            float o0, o1; upk2(acc[i][j], o0, o1);
            *(float2*)&C[(m0 + ty * 8 + i) * 512 + col] =
                make_float2(o0 + bb.x, o1 + bb.y);
        }
    }
}

__global__ __launch_bounds__(256) void sgemm_big3(
    const float* __restrict__ Aq, const float2* __restrict__ Sq, const float* __restrict__ W1q, const float* __restrict__ B1q, const float* __restrict__ Wq, const float* __restrict__ Bq, float* __restrict__ Cq,
    const float* __restrict__ Ak, const float2* __restrict__ Sk, const float* __restrict__ W1k, const float* __restrict__ B1k, const float* __restrict__ Wk, const float* __restrict__ Bk, float* __restrict__ Ck,
    const float* __restrict__ Av, const float2* __restrict__ Sv, const float* __restrict__ W1v, const float* __restrict__ B1v, const float* __restrict__ Wv, const float* __restrict__ Bv, float* __restrict__ Cv)
{
    const int bx = blockIdx.x;
    const int n0 = blockIdx.y * 128;
    if (bx < 8)
        sgemm_big_body_ln(Aq, Sq, W1q, B1q, Wq, Bq, Cq, (size_t)bx * 128, n0);
    else if (bx < 72)
        sgemm_big_body_ln(Ak, Sk, W1k, B1k, Wk, Bk, Ck, (size_t)(bx - 8) * 128, n0);
    else
        sgemm_big_body_ln(Av, Sv, W1v, B1v, Wv, Bv, Cv, (size_t)(bx - 72) * 128, n0);
}

// ---------------------------------------------------------------------------
// Tail GEMM, 4-way split-K with atomic accumulation into pre-zeroed C.
// 32x128 tile, 256 threads, 2x8 thread tile, optional fused LN.
// grid (M/32, 4, 4); blockIdx.z = K quarter (128 each). Split 0 adds bias.
// ---------------------------------------------------------------------------
__global__ __launch_bounds__(256) void sgemm_tail(
    const float* __restrict__ A, const float* __restrict__ B,
    const float* __restrict__ bias, float* __restrict__ C,
    const float2* __restrict__ stats, const float* __restrict__ lnw,
    const float* __restrict__ lnb, int do_ln)
{
    __shared__ float As[2][16][36];
    __shared__ float Bs[2][16][132];

    const int tid = threadIdx.x;
    const int ty = tid >> 4;
    const int tx = tid & 15;
    const size_t m0 = (size_t)blockIdx.x * 32;
    const int n0 = blockIdx.y * 128;
    const int kbase = blockIdx.z * 128;

    const int ar  = tid >> 2;
    const int ak4 = (tid & 3) * 4;
    const int bk  = tid >> 4;
    const int bn  = (tid & 15) * 8;
    const bool aload = tid < 128;

    float2 st = make_float2(0.f, 1.f);
    if (do_ln && aload) st = stats[m0 + ar];

    u64 acc[2][4];
    #pragma unroll
    for (int i = 0; i < 2; ++i)
        #pragma unroll
        for (int j = 0; j < 4; ++j) acc[i][j] = 0ull;

    float4 la = make_float4(0, 0, 0, 0);
    float4 lb0, lb1;
    if (aload) {
        float4 r = *(const float4*)&A[(m0 + ar) * 512 + kbase + ak4];
        if (do_ln) {
            float4 w = *(const float4*)&lnw[kbase + ak4];
            float4 b = *(const float4*)&lnb[kbase + ak4];
            la.x = (r.x - st.x) * st.y * w.x + b.x;
            la.y = (r.y - st.x) * st.y * w.y + b.y;
            la.z = (r.z - st.x) * st.y * w.z + b.z;
            la.w = (r.w - st.x) * st.y * w.w + b.w;
        } else la = r;
    }
    lb0 = *(const float4*)&B[(size_t)(kbase + bk) * 512 + n0 + bn];
    lb1 = *(const float4*)&B[(size_t)(kbase + bk) * 512 + n0 + bn + 4];
    if (aload) {
        As[0][ak4 + 0][ar] = la.x; As[0][ak4 + 1][ar] = la.y;
        As[0][ak4 + 2][ar] = la.z; As[0][ak4 + 3][ar] = la.w;
    }
    *(float4*)&Bs[0][bk][bn]     = lb0;
    *(float4*)&Bs[0][bk][bn + 4] = lb1;
    __syncthreads();

    for (int kt = 0; kt < 8; ++kt) {
        const int buf = kt & 1;
        if (kt < 7) {
            const int k0 = kbase + (kt + 1) * 16;
            if (aload) {
                float4 r = *(const float4*)&A[(m0 + ar) * 512 + k0 + ak4];
                if (do_ln) {
                    float4 w = *(const float4*)&lnw[k0 + ak4];
                    float4 b = *(const float4*)&lnb[k0 + ak4];
                    la.x = (r.x - st.x) * st.y * w.x + b.x;
                    la.y = (r.y - st.x) * st.y * w.y + b.y;
                    la.z = (r.z - st.x) * st.y * w.z + b.z;
                    la.w = (r.w - st.x) * st.y * w.w + b.w;
                } else la = r;
            }
            lb0 = *(const float4*)&B[(size_t)(k0 + bk) * 512 + n0 + bn];
            lb1 = *(const float4*)&B[(size_t)(k0 + bk) * 512 + n0 + bn + 4];
        }
        #pragma unroll
        for (int kk = 0; kk < 16; ++kk) {
            float2 a = *(const float2*)&As[buf][kk][ty * 2];
            u64 b0 = *(const u64*)&Bs[buf][kk][2 * tx];
            u64 b1 = *(const u64*)&Bs[buf][kk][2 * tx + 32];
            u64 b2 = *(const u64*)&Bs[buf][kk][2 * tx + 64];
            u64 b3 = *(const u64*)&Bs[buf][kk][2 * tx + 96];
            u64 a0 = pk2(a.x, a.x), a1 = pk2(a.y, a.y);
            acc[0][0] = fma2(a0, b0, acc[0][0]);
            acc[0][1] = fma2(a0, b1, acc[0][1]);
            acc[0][2] = fma2(a0, b2, acc[0][2]);
            acc[0][3] = fma2(a0, b3, acc[0][3]);
            acc[1][0] = fma2(a1, b0, acc[1][0]);
            acc[1][1] = fma2(a1, b1, acc[1][1]);
            acc[1][2] = fma2(a1, b2, acc[1][2]);
            acc[1][3] = fma2(a1, b3, acc[1][3]);
        }
        if (kt < 7) {
            const int nb = 1 - buf;
            if (aload) {
                As[nb][ak4 + 0][ar] = la.x; As[nb][ak4 + 1][ar] = la.y;
                As[nb][ak4 + 2][ar] = la.z; As[nb][ak4 + 3][ar] = la.w;
            }
            *(float4*)&Bs[nb][bk][bn]     = lb0;
            *(float4*)&Bs[nb][bk][bn + 4] = lb1;
        }
        __syncthreads();
    }

    const bool addb = (blockIdx.z == 0);
    #pragma unroll
    for (int j = 0; j < 4; ++j) {
        const int col = n0 + 2 * tx + 32 * j;
        float2 bb = addb ? *(const float2*)&bias[col] : make_float2(0.f, 0.f);
        #pragma unroll
        for (int i = 0; i < 2; ++i) {
            float o0, o1; upk2(acc[i][j], o0, o1);
            float* cp = &C[(m0 + ty * 2 + i) * 512 + col];
            atomicAdd(cp,     o0 + bb.x);
            atomicAdd(cp + 1, o1 + bb.y);
        }
    }
}

// ---------------------------------------------------------------------------
// Fused ColBERT attention (R14/R15, best measured). Block 256 thr / 8 warps,
// grid (16, 8). 64-token tile, 8 rows/warp, 2 chunks per barrier period
// with 4 K/V buffers. Per-lane l, pk2-AV, Q pre-scaled.
// smem floats: qs[4096] | ks 4x[8192] | vs 4x[2048] | pd[2048] = 47104
// ---------------------------------------------------------------------------
#define ATT_SMEM (47104 * 4)

__global__ __launch_bounds__(256) void attn_kernel(
    const float* __restrict__ q, const float* __restrict__ k,
    const float* __restrict__ v, float* __restrict__ outp)
{
    extern __shared__ float sm[];
    float* qs  = sm;             // [64][64], pre-scaled by 0.125
    float* ksb = sm + 4096;      // 4 x [u][cc][64] swizzled
    float* vsb = sm + 36864;     // 4 x [cc][64]
    float* pd  = sm + 45056;     // [warp][cc][8]

    const int tid  = threadIdx.x;
    const int w    = tid >> 5;
    const int lane = tid & 31;
    const int h    = blockIdx.y;
    const int bt0  = blockIdx.x * 64;
    const int r0   = w * 8;
    const int sw   = (lane & 7) << 2;
    const uint32_t smb = smem_u32(sm);

    const int scc = tid >> 3, srr = tid & 7;
    const float* kg = k + ((size_t)scc * 4) * 512 + h * 64 + srr * 4;
    const uint32_t koff0 = (uint32_t)(scc * 64 + ((srr * 4) ^ ((scc & 7) << 2)));
    const float* vg = v + (size_t)(tid >> 4) * 512 + h * 64 + (tid & 15) * 4;
    const uint32_t voff0 = (uint32_t)((tid >> 4) * 64 + (tid & 15) * 4);

    // Q staging with 1/8 scale folded in: 1024 float4
    #pragma unroll
    for (int j = 0; j < 4; ++j) {
        int i = tid + 256 * j;
        int dd = i & 15, r = i >> 4;
        float4 t = *(const float4*)&q[(size_t)(bt0 + r) * 512 + h * 64 + dd * 4];
        *(float4*)&qs[r * 64 + dd * 4] =
            make_float4(t.x * 0.125f, t.y * 0.125f, t.z * 0.125f, t.w * 0.125f);
    }

    auto stage = [&](int b, int c) {
        const float* kp = kg + (size_t)c * 65536;
        const uint32_t kd = smb + (4096 + b * 8192 + koff0) * 4;
        #pragma unroll
        for (int j = 0; j < 8; ++j)
            CP_ASYNC16(kd + (uint32_t)(((j & 1) * 32 + (j >> 1) * 2048) * 4),
                       kp + (j >> 1) * 512 + (j & 1) * 32);
        const float* vp = vg + (size_t)c * 16384;
        const uint32_t vd = smb + (36864 + b * 2048 + voff0) * 4;
        CP_ASYNC16(vd, vp);
        CP_ASYNC16(vd + 1024 * 4, vp + 8192);
    };

    float m[8], lp[8];          // lp = per-lane partial denominator
    u64 o2[8];
    #pragma unroll
    for (int r = 0; r < 8; ++r) { m[r] = -1e30f; lp[r] = 0.f; o2[r] = 0ull; }

    float* pw = pd + w * 256;

    auto compute = [&](int buf) {
        const float* ks = ksb + buf * 8192;
        const float* vs = vsb + buf * 2048;
        const float* kb = ks + lane * 64;

        u64 acc[8][4];
        #pragma unroll
        for (int r = 0; r < 8; ++r)
            #pragma unroll
            for (int u = 0; u < 4; ++u) acc[r][u] = 0ull;

        #pragma unroll
        for (int d4 = 0; d4 < 64; d4 += 4) {
            const int off = d4 ^ sw;
            ulonglong2 k0 = *(const ulonglong2*)&kb[off];
            ulonglong2 k1 = *(const ulonglong2*)&kb[off + 2048];
            ulonglong2 k2 = *(const ulonglong2*)&kb[off + 4096];
            ulonglong2 k3 = *(const ulonglong2*)&kb[off + 6144];
            #pragma unroll
            for (int r = 0; r < 8; ++r) {
                ulonglong2 qq = *(const ulonglong2*)&qs[(r0 + r) * 64 + d4];
                acc[r][0] = fma2(qq.x, k0.x, acc[r][0]);
                acc[r][0] = fma2(qq.y, k0.y, acc[r][0]);
                acc[r][1] = fma2(qq.x, k1.x, acc[r][1]);
                acc[r][1] = fma2(qq.y, k1.y, acc[r][1]);
                acc[r][2] = fma2(qq.x, k2.x, acc[r][2]);
                acc[r][2] = fma2(qq.y, k2.y, acc[r][2]);
                acc[r][3] = fma2(qq.x, k3.x, acc[r][3]);
                acc[r][3] = fma2(qq.y, k3.y, acc[r][3]);
            }
        }

        float pv[8];
        #pragma unroll
        for (int r = 0; r < 8; ++r) {
            float x0, x1, s;
            upk2(acc[r][0], x0, x1); s = x0 + x1;
            upk2(acc[r][1], x0, x1); s = fmaxf(s, x0 + x1);
            upk2(acc[r][2], x0, x1); s = fmaxf(s, x0 + x1);
            upk2(acc[r][3], x0, x1); s = fmaxf(s, x0 + x1);
            float cm = s;
            #pragma unroll
            for (int o = 16; o; o >>= 1)
                cm = fmaxf(cm, __shfl_xor_sync(0xffffffffu, cm, o));
            float mn   = fmaxf(m[r], cm);
            float corr = __expf(m[r] - mn);
            pv[r] = __expf(s - mn);
            lp[r] = lp[r] * corr + pv[r];
            m[r] = mn;
            o2[r] = mul2(o2[r], pk2(corr, corr));
        }

        *(float4*)&pw[lane * 8]     = make_float4(pv[0], pv[1], pv[2], pv[3]);
        *(float4*)&pw[lane * 8 + 4] = make_float4(pv[4], pv[5], pv[6], pv[7]);
        __syncwarp();

        #pragma unroll
        for (int j = 0; j < 32; ++j) {
            u64 vj = *(const u64*)&vs[j * 64 + 2 * lane];
            float4 pa = *(const float4*)&pw[j * 8];
            float4 pb = *(const float4*)&pw[j * 8 + 4];
            o2[0] = fma2(pk2(pa.x, pa.x), vj, o2[0]);
            o2[1] = fma2(pk2(pa.y, pa.y), vj, o2[1]);
            o2[2] = fma2(pk2(pa.z, pa.z), vj, o2[2]);
            o2[3] = fma2(pk2(pa.w, pa.w), vj, o2[3]);
            o2[4] = fma2(pk2(pb.x, pb.x), vj, o2[4]);
            o2[5] = fma2(pk2(pb.y, pb.y), vj, o2[5]);
            o2[6] = fma2(pk2(pb.z, pb.z), vj, o2[6]);
            o2[7] = fma2(pk2(pb.w, pb.w), vj, o2[7]);
        }
        __syncwarp();
    };

    // prologue: pair 0 (chunks 0,1) into buffers {0,1}
    stage(0, 0); stage(1, 1); CP_COMMIT();

    for (int p = 0; p < 32; ++p) {
        const int b0 = 2 * (p & 1);
        if (p < 31) {
            const int nb = 2 * ((p + 1) & 1);
            stage(nb, 2 * (p + 1));
            stage(nb + 1, 2 * (p + 1) + 1);
            CP_COMMIT();
            CP_WAIT(1);
        } else {
            CP_WAIT(0);
        }
        __syncthreads();
        compute(b0);
        compute(b0 + 1);
        __syncthreads();
    }

    // ---- final l reduce + normalize + write
    #pragma unroll
    for (int r = 0; r < 8; ++r) {
        float ls = lp[r];
        #pragma unroll
        for (int o = 16; o; o >>= 1)
            ls += __shfl_xor_sync(0xffffffffu, ls, o);
        float inv = 1.f / ls;
        float lo, hi; upk2(o2[r], lo, hi);
        *(float2*)&outp[(size_t)(bt0 + r0 + r) * 512 + h * 64 + 2 * lane] =
            make_float2(lo * inv, hi * inv);
    }
}

// ---------------------------------------------------------------------------
extern "C" void kernel_launch(void* const* d_in, const int* in_sizes, int n_in,
                              void* d_out, int out_size)
{
    const float* model_embed = (const float*)d_in[0];
    const float* ctx_key     = (const float*)d_in[1];
    const float* ctx_val     = (const float*)d_in[2];
    const float* ln1w = (const float*)d_in[3];
    const float* ln1b = (const float*)d_in[4];
    const float* ln2w = (const float*)d_in[5];
    const float* ln2b = (const float*)d_in[6];
    const float* ln3w = (const float*)d_in[7];
    const float* ln3b = (const float*)d_in[8];
    const float* ln4w = (const float*)d_in[9];
    const float* ln4b = (const float*)d_in[10];
    const float* wq = (const float*)d_in[11];
    const float* bq = (const float*)d_in[12];
    const float* wk = (const float*)d_in[13];
    const float* bk = (const float*)d_in[14];
    const float* wv = (const float*)d_in[15];
    const float* bv = (const float*)d_in[16];
    const float* wo = (const float*)d_in[17];
    const float* bo = (const float*)d_in[18];
    const float* wp = (const float*)d_in[19];
    const float* bp = (const float*)d_in[20];

    float2 *stats, *stats4;
    float *q, *k, *v, *att, *o;
    cudaGetSymbolAddress((void**)&stats,  g_stats);
    cudaGetSymbolAddress((void**)&stats4, g_stats4);
    cudaGetSymbolAddress((void**)&q,    g_q);
    cudaGetSymbolAddress((void**)&k,    g_k);
    cudaGetSymbolAddress((void**)&v,    g_v);
    cudaGetSymbolAddress((void**)&att,  g_att);
    cudaGetSymbolAddress((void**)&o,    g_o);

    static int attr_set = 0;
    if (!attr_set) {
        cudaFuncSetAttribute(attn_kernel,
                             cudaFuncAttributeMaxDynamicSharedMemorySize, ATT_SMEM);
        attr_set = 1;
    }

    // LN stats (+ fused zeroing of atomic targets) + LN+GEMM projections
    ln_stats3<<<1408, 256>>>(model_embed, ctx_key, ctx_val, stats,
                             o, (float*)d_out);
    sgemm_big3<<<dim3(88, 4), 256>>>(
        model_embed, stats,        ln1w, ln1b, wq, bq, q,
        ctx_key,     stats + 1024, ln2w, ln2b, wk, bk, k,
        ctx_val,     stats + 9216, ln3w, ln3b, wv, bv, v);

    // fused MaxSim attention
    attn_kernel<<<dim3(16, 8), 256, ATT_SMEM>>>(q, k, v, att);

    // output proj (split-K 4x), LN4 stats, final proj (split-K 4x, fused LN)
    sgemm_tail<<<dim3(32, 4, 4), 256>>>(att, wo, bo, o, nullptr, nullptr, nullptr, 0);
    ln_stats1<<<128, 256>>>(o, stats4);
    sgemm_tail<<<dim3(32, 4, 4), 256>>>(o, wp, bp, (float*)d_out, stats4, ln4w, ln4b, 1);
}